// round 1
// baseline (speedup 1.0000x reference)
#include <cuda_runtime.h>
#include <math.h>

// ---------------- problem constants (fixed shapes) ----------------
#define N_NODES 50000
#define N_EDGES 800000
#define FN 92
#define FE 41
#define D 64
#define DIN 169            // 2*D + FE
#define NG 100
#define HDIM 128
#define NLAYERS 3
#define BN_EPS 1e-5f

// ---------------- device scratch (static, allowed) ----------------
__device__ float sc_v[N_NODES * D];          // node features (current)
__device__ float sc_y[N_EDGES * 2 * D];      // edge pre-activations [E][128]: cols 0..63 = m path, 64..127 = s path
__device__ float sc_agg[N_NODES * D];        // scatter target
__device__ float sc_sum[2 * D];              // per-feature sums
__device__ float sc_ssq[2 * D];              // per-feature sum of squares
__device__ float sc_scale[2 * D];            // BN scale
__device__ float sc_shift[2 * D];            // BN shift
__device__ float sc_pool[NG * D];
__device__ float sc_cnt[NG];
__device__ float sc_fcbuf[NG * HDIM];

// ---------------- math helpers ----------------
__device__ __forceinline__ float sigmoid_f(float x) { return 1.0f / (1.0f + __expf(-x)); }
__device__ __forceinline__ float softplus_f(float x) {
    return fmaxf(x, 0.0f) + log1pf(__expf(-fabsf(x)));
}

// ---------------- zero kernels ----------------
__global__ void zero_stats_kernel() {
    int t = threadIdx.x;
    if (t < 2 * D) { sc_sum[t] = 0.0f; sc_ssq[t] = 0.0f; }
}
__global__ void zero_agg_kernel() {
    int i = blockIdx.x * blockDim.x + threadIdx.x;
    if (i < N_NODES * D) sc_agg[i] = 0.0f;
}
__global__ void zero_pool_kernel() {
    int i = blockIdx.x * blockDim.x + threadIdx.x;
    if (i < NG * D) sc_pool[i] = 0.0f;
    if (i < NG) sc_cnt[i] = 0.0f;
}

// ---------------- BN scale/shift from raw stats ----------------
// scale = gamma * rsqrt(var + eps); shift = beta - mu * scale
__global__ void scale_kernel(const float* __restrict__ gamma, const float* __restrict__ beta,
                             float count, int off) {
    int t = threadIdx.x;  // 64 threads
    float mu = sc_sum[off + t] / count;
    float var = fmaxf(sc_ssq[off + t] / count - mu * mu, 0.0f);
    float s = gamma[t] * rsqrtf(var + BN_EPS);
    sc_scale[off + t] = s;
    sc_shift[off + t] = beta[t] - mu * s;
}

// ---------------- node embedding GEMM: [N,92]@[92,64] + b, stats into sc_sum/sc_ssq[0..63] ----------------
__global__ __launch_bounds__(256) void emb_kernel(const float* __restrict__ x,
                                                  const float* __restrict__ W,
                                                  const float* __restrict__ b) {
    __shared__ float Wsh[FN * D];
    __shared__ float xsh[4][FN];
    __shared__ float red[256];
    int t = threadIdx.x;
    for (int i = t; i < FN * D; i += 256) Wsh[i] = W[i];
    int c = t & 63, rs = t >> 6;
    float bc = b[c];
    float ls = 0.0f, lq = 0.0f;
    const int ntiles = N_NODES / 4;
    for (int ti = blockIdx.x; ti < ntiles; ti += gridDim.x) {
        int r0 = ti * 4;
        __syncthreads();
        for (int i = t; i < 4 * FN; i += 256) {
            int rr = i / FN, k = i - rr * FN;
            xsh[rr][k] = x[(r0 + rr) * FN + k];
        }
        __syncthreads();
        float acc = bc;
#pragma unroll 4
        for (int k = 0; k < FN; k++) acc += xsh[rs][k] * Wsh[k * D + c];
        sc_v[(r0 + rs) * D + c] = acc;
        ls += acc; lq += acc * acc;
    }
    __syncthreads();
    red[t] = ls; __syncthreads();
    if (t < 64) atomicAdd(&sc_sum[t], red[t] + red[t + 64] + red[t + 128] + red[t + 192]);
    __syncthreads();
    red[t] = lq; __syncthreads();
    if (t < 64) atomicAdd(&sc_ssq[t], red[t] + red[t + 64] + red[t + 128] + red[t + 192]);
}

// v = silu(v*scale + shift)
__global__ void silu_apply_kernel() {
    int idx = blockIdx.x * blockDim.x + threadIdx.x;
    if (idx < N_NODES * D) {
        int c = idx & 63;
        float y = sc_v[idx] * sc_scale[c] + sc_shift[c];
        sc_v[idx] = y * sigmoid_f(y);
    }
}

// ---------------- edge GEMM: y[e][coloff + 0..63] = h[e] @ W (169x64) + b ----------------
// h[e] = [v[src[e]] (64) || v[dst[e]] (64) || edge_feats[e] (41)]
// Register blocking: 256 threads = 8 col-groups (8 cols each) x 32 edge-pairs (2 edges each)
// Tile: 64 edges per block iteration. Also accumulates BN stats.
#define EG_SMEM_BYTES ((DIN * D + 64 * (DIN + 1)) * 4)
__global__ __launch_bounds__(256, 2) void edge_gemm_kernel(const float* __restrict__ ef,
                                                           const int* __restrict__ src,
                                                           const int* __restrict__ dst,
                                                           const float* __restrict__ W,
                                                           const float* __restrict__ b,
                                                           int coloff) {
    extern __shared__ float sm[];
    float* Wsh = sm;                 // DIN*D floats
    float* hsh = sm + DIN * D;       // 64 * (DIN+1) floats
    __shared__ int ssrc[64], sdst[64];
    int t = threadIdx.x;
    for (int i = t; i < DIN * D; i += 256) Wsh[i] = W[i];
    int cg = t & 7;        // col group 0..7
    int eq = t >> 3;       // edge pair 0..31
    int c0 = cg * 8;
    float bb[8];
#pragma unroll
    for (int j = 0; j < 8; j++) bb[j] = b[c0 + j];
    float lsum[8], lssq[8];
#pragma unroll
    for (int j = 0; j < 8; j++) { lsum[j] = 0.0f; lssq[j] = 0.0f; }

    const int ntiles = N_EDGES / 64;
    for (int ti = blockIdx.x; ti < ntiles; ti += gridDim.x) {
        int e0 = ti * 64;
        __syncthreads();
        if (t < 64) ssrc[t] = src[e0 + t];
        else if (t < 128) sdst[t - 64] = dst[e0 + t - 64];
        __syncthreads();
        // stage h tile [64][169]
        for (int i = t; i < 64 * DIN; i += 256) {
            int le = i / DIN, k = i - le * DIN;
            float val;
            if (k < D)            val = sc_v[ssrc[le] * D + k];
            else if (k < 2 * D)   val = sc_v[sdst[le] * D + (k - D)];
            else                  val = ef[(e0 + le) * FE + (k - 2 * D)];
            hsh[le * (DIN + 1) + k] = val;
        }
        __syncthreads();

        float a0[8], a1[8];
#pragma unroll
        for (int j = 0; j < 8; j++) { a0[j] = 0.0f; a1[j] = 0.0f; }
        const float* h0p = &hsh[eq * (DIN + 1)];
        const float* h1p = &hsh[(eq + 32) * (DIN + 1)];
#pragma unroll 13
        for (int k = 0; k < DIN; k++) {
            float h0 = h0p[k];
            float h1 = h1p[k];
            float4 w0 = *(const float4*)&Wsh[k * D + c0];
            float4 w1 = *(const float4*)&Wsh[k * D + c0 + 4];
            a0[0] += h0 * w0.x; a0[1] += h0 * w0.y; a0[2] += h0 * w0.z; a0[3] += h0 * w0.w;
            a0[4] += h0 * w1.x; a0[5] += h0 * w1.y; a0[6] += h0 * w1.z; a0[7] += h0 * w1.w;
            a1[0] += h1 * w0.x; a1[1] += h1 * w0.y; a1[2] += h1 * w0.z; a1[3] += h1 * w0.w;
            a1[4] += h1 * w1.x; a1[5] += h1 * w1.y; a1[6] += h1 * w1.z; a1[7] += h1 * w1.w;
        }
#pragma unroll
        for (int j = 0; j < 8; j++) {
            float y0 = a0[j] + bb[j];
            float y1 = a1[j] + bb[j];
            a0[j] = y0; a1[j] = y1;
            lsum[j] += y0 + y1;
            lssq[j] += y0 * y0 + y1 * y1;
        }
        float* o0 = &sc_y[(e0 + eq) * 128 + coloff + c0];
        float* o1 = &sc_y[(e0 + eq + 32) * 128 + coloff + c0];
        *(float4*)(o0)     = make_float4(a0[0], a0[1], a0[2], a0[3]);
        *(float4*)(o0 + 4) = make_float4(a0[4], a0[5], a0[6], a0[7]);
        *(float4*)(o1)     = make_float4(a1[0], a1[1], a1[2], a1[3]);
        *(float4*)(o1 + 4) = make_float4(a1[4], a1[5], a1[6], a1[7]);
    }

    // block-reduce stats, reuse hsh as scratch (needs 32*64 = 2048 floats)
    __syncthreads();
    float* red = hsh;
#pragma unroll
    for (int j = 0; j < 8; j++) red[eq * 64 + c0 + j] = lsum[j];
    __syncthreads();
    if (t < 64) {
        float s = 0.0f;
        for (int q = 0; q < 32; q++) s += red[q * 64 + t];
        atomicAdd(&sc_sum[coloff + t], s);
    }
    __syncthreads();
#pragma unroll
    for (int j = 0; j < 8; j++) red[eq * 64 + c0 + j] = lssq[j];
    __syncthreads();
    if (t < 64) {
        float s = 0.0f;
        for (int q = 0; q < 32; q++) s += red[q * 64 + t];
        atomicAdd(&sc_ssq[coloff + t], s);
    }
}

// ---------------- apply edge BN + gate, scatter to agg ----------------
__global__ void edge_apply_kernel(const int* __restrict__ dst) {
    int idx = blockIdx.x * blockDim.x + threadIdx.x;
    if (idx >= N_EDGES * D) return;
    int c = idx & 63;
    int e = idx >> 6;
    float ym = sc_y[e * 128 + c];
    float ys = sc_y[e * 128 + 64 + c];
    float m = sigmoid_f(ym * sc_scale[c] + sc_shift[c]);
    float xs = ys * sc_scale[64 + c] + sc_shift[64 + c];
    float s = softplus_f(xs);
    atomicAdd(&sc_agg[dst[e] * D + c], m * s);
}

// ---------------- column stats of agg ----------------
__global__ __launch_bounds__(256) void node_stats_kernel() {
    __shared__ float red[256];
    int t = threadIdx.x;
    int c = t & 63, rs = t >> 6;
    float ls = 0.0f, lq = 0.0f;
    const int ntiles = N_NODES / 4;
    for (int ti = blockIdx.x; ti < ntiles; ti += gridDim.x) {
        float y = sc_agg[(ti * 4 + rs) * D + c];
        ls += y; lq += y * y;
    }
    red[t] = ls; __syncthreads();
    if (t < 64) atomicAdd(&sc_sum[t], red[t] + red[t + 64] + red[t + 128] + red[t + 192]);
    __syncthreads();
    red[t] = lq; __syncthreads();
    if (t < 64) atomicAdd(&sc_ssq[t], red[t] + red[t + 64] + red[t + 128] + red[t + 192]);
}

// v = softplus(bn(agg) + v)
__global__ void node_apply_kernel() {
    int idx = blockIdx.x * blockDim.x + threadIdx.x;
    if (idx < N_NODES * D) {
        int c = idx & 63;
        float x = sc_agg[idx] * sc_scale[c] + sc_shift[c] + sc_v[idx];
        sc_v[idx] = softplus_f(x);
    }
}

// ---------------- graph average pooling ----------------
__global__ void pool_kernel(const int* __restrict__ gid) {
    int idx = blockIdx.x * blockDim.x + threadIdx.x;
    if (idx >= N_NODES * D) return;
    int c = idx & 63;
    int n = idx >> 6;
    int g = gid[n];
    atomicAdd(&sc_pool[g * D + c], sc_v[idx]);
    if (c == 0) atomicAdd(&sc_cnt[g], 1.0f);
}
__global__ void pool_finish_kernel() {
    int idx = blockIdx.x * blockDim.x + threadIdx.x;
    if (idx < NG * D) {
        int g = idx >> 6;
        sc_pool[idx] /= fmaxf(sc_cnt[g], 1.0f);
    }
}

// ---------------- fc + BN + silu + regression head (single block, 128 threads) ----------------
__global__ __launch_bounds__(128) void fc_kernel(const float* __restrict__ Wfc, const float* __restrict__ bfc,
                                                 const float* __restrict__ gfc, const float* __restrict__ befc,
                                                 const float* __restrict__ Wout, const float* __restrict__ bout,
                                                 float* __restrict__ out) {
    __shared__ float psh[NG * D];
    __shared__ float red[128];
    int c = threadIdx.x;
    for (int i = c; i < NG * D; i += 128) psh[i] = sc_pool[i];
    __syncthreads();
    float s = 0.0f, q = 0.0f;
    float bc = bfc[c];
    for (int g = 0; g < NG; g++) {
        float acc = bc;
#pragma unroll 8
        for (int k = 0; k < D; k++) acc += psh[g * D + k] * Wfc[k * HDIM + c];
        sc_fcbuf[g * HDIM + c] = acc;
        s += acc; q += acc * acc;
    }
    float mu = s / (float)NG;
    float var = fmaxf(q / (float)NG - mu * mu, 0.0f);
    float sc = gfc[c] * rsqrtf(var + BN_EPS);
    float sh = befc[c] - mu * sc;
    float wo = Wout[c];
    float b0 = bout[0];
    for (int g = 0; g < NG; g++) {
        float y = sc_fcbuf[g * HDIM + c] * sc + sh;
        float val = y * sigmoid_f(y) * wo;
        red[c] = val; __syncthreads();
        for (int st = 64; st > 0; st >>= 1) {
            if (c < st) red[c] += red[c + st];
            __syncthreads();
        }
        if (c == 0) out[g] = red[0] + b0;
        __syncthreads();
    }
}

// ---------------- host launch ----------------
extern "C" void kernel_launch(void* const* d_in, const int* in_sizes, int n_in,
                              void* d_out, int out_size) {
    const float* node_feats = (const float*)d_in[0];
    const float* edge_feats = (const float*)d_in[1];
    const int*   src        = (const int*)d_in[2];
    const int*   dst        = (const int*)d_in[3];
    const int*   gid        = (const int*)d_in[4];
    const float* W_emb  = (const float*)d_in[5];
    const float* b_emb  = (const float*)d_in[6];
    const float* g_emb  = (const float*)d_in[7];
    const float* be_emb = (const float*)d_in[8];
    const float* conv_Wm  = (const float*)d_in[9];
    const float* conv_bm  = (const float*)d_in[10];
    const float* conv_gm  = (const float*)d_in[11];
    const float* conv_bem = (const float*)d_in[12];
    const float* conv_Ws  = (const float*)d_in[13];
    const float* conv_bs  = (const float*)d_in[14];
    const float* conv_gs  = (const float*)d_in[15];
    const float* conv_bes = (const float*)d_in[16];
    const float* conv_gn  = (const float*)d_in[17];
    const float* conv_ben = (const float*)d_in[18];
    const float* W_fc  = (const float*)d_in[19];
    const float* b_fc  = (const float*)d_in[20];
    const float* g_fc  = (const float*)d_in[21];
    const float* be_fc = (const float*)d_in[22];
    const float* W_out = (const float*)d_in[23];
    const float* b_out = (const float*)d_in[24];
    float* out = (float*)d_out;

    cudaFuncSetAttribute(edge_gemm_kernel, cudaFuncAttributeMaxDynamicSharedMemorySize, EG_SMEM_BYTES);

    const int ND = N_NODES * D;
    const int ED = N_EDGES * D;
    const int TB = 256;

    // embedding: v = silu(bn(x @ W_emb + b_emb))
    zero_stats_kernel<<<1, 128>>>();
    emb_kernel<<<512, 256>>>(node_feats, W_emb, b_emb);
    scale_kernel<<<1, 64>>>(g_emb, be_emb, (float)N_NODES, 0);
    silu_apply_kernel<<<(ND + TB - 1) / TB, TB>>>();

    for (int l = 0; l < NLAYERS; l++) {
        zero_stats_kernel<<<1, 128>>>();
        edge_gemm_kernel<<<296, 256, EG_SMEM_BYTES>>>(edge_feats, src, dst,
            conv_Wm + l * DIN * D, conv_bm + l * D, 0);
        edge_gemm_kernel<<<296, 256, EG_SMEM_BYTES>>>(edge_feats, src, dst,
            conv_Ws + l * DIN * D, conv_bs + l * D, 64);
        scale_kernel<<<1, 64>>>(conv_gm + l * D, conv_bem + l * D, (float)N_EDGES, 0);
        scale_kernel<<<1, 64>>>(conv_gs + l * D, conv_bes + l * D, (float)N_EDGES, 64);
        zero_agg_kernel<<<(ND + TB - 1) / TB, TB>>>();
        edge_apply_kernel<<<(ED + TB - 1) / TB, TB>>>(dst);
        zero_stats_kernel<<<1, 128>>>();
        node_stats_kernel<<<256, 256>>>();
        scale_kernel<<<1, 64>>>(conv_gn + l * D, conv_ben + l * D, (float)N_NODES, 0);
        node_apply_kernel<<<(ND + TB - 1) / TB, TB>>>();
    }

    // pooling + fc + head
    zero_pool_kernel<<<(NG * D + TB - 1) / TB, TB>>>();
    pool_kernel<<<(ND + TB - 1) / TB, TB>>>(gid);
    pool_finish_kernel<<<(NG * D + TB - 1) / TB, TB>>>();
    fc_kernel<<<1, 128>>>(W_fc, b_fc, g_fc, be_fc, W_out, b_out, out);
}

// round 2
// speedup vs baseline: 1.6568x; 1.6568x over previous
#include <cuda_runtime.h>
#include <math.h>

// ---------------- problem constants (fixed shapes) ----------------
#define N_NODES 50000
#define N_EDGES 800000
#define FN 92
#define FE 41
#define D 64
#define DIN 169            // 2*D + FE
#define NG 100
#define HDIM 128
#define NLAYERS 3
#define BN_EPS 1e-5f

// ---------------- device scratch (static, allowed) ----------------
__device__ float sc_v[N_NODES * D];          // node features (current)
__device__ float sc_y[N_EDGES * 2 * D];      // edge pre-activations [E][128]: 0..63 = m path, 64..127 = s path
__device__ float sc_agg[N_NODES * D];        // scatter target
__device__ float sc_sum[2 * D];              // per-feature sums
__device__ float sc_ssq[2 * D];              // per-feature sum of squares
__device__ float sc_scale[2 * D];            // BN scale
__device__ float sc_shift[2 * D];            // BN shift
__device__ float sc_pool[NG * D];
__device__ float sc_cnt[NG];
__device__ float sc_fcbuf[NG * HDIM];

// ---------------- math helpers ----------------
__device__ __forceinline__ float sigmoid_f(float x) { return 1.0f / (1.0f + __expf(-x)); }
__device__ __forceinline__ float softplus_f(float x) {
    return fmaxf(x, 0.0f) + log1pf(__expf(-fabsf(x)));
}
__device__ __forceinline__ void red_v4(float* p, float4 v) {
    asm volatile("red.global.add.v4.f32 [%0], {%1,%2,%3,%4};"
                 :: "l"(p), "f"(v.x), "f"(v.y), "f"(v.z), "f"(v.w) : "memory");
}

// ---------------- zero kernels ----------------
__global__ void zero_stats_kernel() {
    int t = threadIdx.x;
    if (t < 2 * D) { sc_sum[t] = 0.0f; sc_ssq[t] = 0.0f; }
}
__global__ void zero_agg_kernel() {
    int i = blockIdx.x * blockDim.x + threadIdx.x;
    if (i < N_NODES * D / 4) ((float4*)sc_agg)[i] = make_float4(0.f, 0.f, 0.f, 0.f);
}
__global__ void zero_pool_kernel() {
    int i = blockIdx.x * blockDim.x + threadIdx.x;
    if (i < NG * D) sc_pool[i] = 0.0f;
    if (i < NG) sc_cnt[i] = 0.0f;
}

// ---------------- BN scale/shift from raw stats ----------------
__global__ void scale_kernel(const float* __restrict__ gamma, const float* __restrict__ beta,
                             float count, int off) {
    int t = threadIdx.x;  // 64 threads
    float mu = sc_sum[off + t] / count;
    float var = fmaxf(sc_ssq[off + t] / count - mu * mu, 0.0f);
    float s = gamma[t] * rsqrtf(var + BN_EPS);
    sc_scale[off + t] = s;
    sc_shift[off + t] = beta[t] - mu * s;
}

// ---------------- node embedding GEMM: [N,92]@[92,64] + b, stats into sc_sum/sc_ssq[0..63] ----------------
__global__ __launch_bounds__(256) void emb_kernel(const float* __restrict__ x,
                                                  const float* __restrict__ W,
                                                  const float* __restrict__ b) {
    __shared__ float Wsh[FN * D];
    __shared__ float xsh[4][FN];
    __shared__ float red[256];
    int t = threadIdx.x;
    for (int i = t; i < FN * D; i += 256) Wsh[i] = W[i];
    int c = t & 63, rs = t >> 6;
    float bc = b[c];
    float ls = 0.0f, lq = 0.0f;
    const int ntiles = N_NODES / 4;
    for (int ti = blockIdx.x; ti < ntiles; ti += gridDim.x) {
        int r0 = ti * 4;
        __syncthreads();
        for (int i = t; i < 4 * FN; i += 256) {
            int rr = i / FN, k = i - rr * FN;
            xsh[rr][k] = x[(r0 + rr) * FN + k];
        }
        __syncthreads();
        float acc = bc;
#pragma unroll 4
        for (int k = 0; k < FN; k++) acc += xsh[rs][k] * Wsh[k * D + c];
        sc_v[(r0 + rs) * D + c] = acc;
        ls += acc; lq += acc * acc;
    }
    __syncthreads();
    red[t] = ls; __syncthreads();
    if (t < 64) atomicAdd(&sc_sum[t], red[t] + red[t + 64] + red[t + 128] + red[t + 192]);
    __syncthreads();
    red[t] = lq; __syncthreads();
    if (t < 64) atomicAdd(&sc_ssq[t], red[t] + red[t + 64] + red[t + 128] + red[t + 192]);
}

// v = silu(v*scale + shift)
__global__ void silu_apply_kernel() {
    int idx = blockIdx.x * blockDim.x + threadIdx.x;
    if (idx < N_NODES * D) {
        int c = idx & 63;
        float y = sc_v[idx] * sc_scale[c] + sc_shift[c];
        sc_v[idx] = y * sigmoid_f(y);
    }
}

// ---------------- fused edge GEMM: y[e][0..127] = h[e] @ [Wm | Ws] + [bm | bs] ----------------
// h[e] = [v[src[e]] (64) || v[dst[e]] (64) || edge_feats[e] (41)]  (169 values)
// Tile: 128 edges x 128 cols. 512 threads = 16 col-groups (8 cols) x 32 edge slots (4 edges).
// W tile (169x128) and h tile (128x170) both in dynamic smem. Accumulates BN stats for all 128 cols.
#define EG2_SMEM_BYTES ((DIN * 128 + 128 * (DIN + 1)) * 4)   // 86528 + 87040 = 173568 B
__global__ __launch_bounds__(512, 1) void edge_gemm2_kernel(const float* __restrict__ ef,
                                                            const int* __restrict__ src,
                                                            const int* __restrict__ dst,
                                                            const float* __restrict__ Wm,
                                                            const float* __restrict__ bm,
                                                            const float* __restrict__ Ws,
                                                            const float* __restrict__ bs) {
    extern __shared__ float sm[];
    float* Wsh = sm;                      // DIN*128 floats
    float* hsh = sm + DIN * 128;          // 128 * (DIN+1) floats
    __shared__ int ssrc[128], sdst[128];
    int t = threadIdx.x;

    // stage fused weights: cols 0..63 = Wm, 64..127 = Ws
    for (int i = t; i < DIN * 128; i += 512) {
        int k = i >> 7, c = i & 127;
        Wsh[i] = (c < 64) ? Wm[k * 64 + c] : Ws[k * 64 + (c - 64)];
    }

    int cg = t & 15;      // col group 0..15 (8 cols each)
    int es = t >> 4;      // edge slot 0..31 (4 edges each: es, es+32, es+64, es+96)
    int c0 = cg * 8;
    float bb[8];
#pragma unroll
    for (int j = 0; j < 8; j++) {
        int c = c0 + j;
        bb[j] = (c < 64) ? bm[c] : bs[c - 64];
    }
    float lsum[8], lssq[8];
#pragma unroll
    for (int j = 0; j < 8; j++) { lsum[j] = 0.0f; lssq[j] = 0.0f; }

    const int ntiles = N_EDGES / 128;     // 6250
    for (int ti = blockIdx.x; ti < ntiles; ti += gridDim.x) {
        int e0 = ti * 128;
        __syncthreads();
        if (t < 128) ssrc[t] = src[e0 + t];
        else if (t < 256) sdst[t - 128] = dst[e0 + t - 128];
        __syncthreads();
        // stage h tile [128][169] (stride 170)
        for (int i = t; i < 128 * DIN; i += 512) {
            int le = i / DIN, k = i - le * DIN;
            float val;
            if (k < D)            val = sc_v[ssrc[le] * D + k];
            else if (k < 2 * D)   val = sc_v[sdst[le] * D + (k - D)];
            else                  val = ef[(e0 + le) * FE + (k - 2 * D)];
            hsh[le * (DIN + 1) + k] = val;
        }
        __syncthreads();

        float a0[8], a1[8], a2[8], a3[8];
#pragma unroll
        for (int j = 0; j < 8; j++) { a0[j] = 0.0f; a1[j] = 0.0f; a2[j] = 0.0f; a3[j] = 0.0f; }
        const float* h0p = &hsh[(es     ) * (DIN + 1)];
        const float* h1p = &hsh[(es + 32) * (DIN + 1)];
        const float* h2p = &hsh[(es + 64) * (DIN + 1)];
        const float* h3p = &hsh[(es + 96) * (DIN + 1)];
#pragma unroll 4
        for (int k = 0; k < DIN; k++) {
            float4 w0 = *(const float4*)&Wsh[k * 128 + c0];
            float4 w1 = *(const float4*)&Wsh[k * 128 + c0 + 4];
            float h0 = h0p[k], h1 = h1p[k], h2 = h2p[k], h3 = h3p[k];
            a0[0] += h0 * w0.x; a0[1] += h0 * w0.y; a0[2] += h0 * w0.z; a0[3] += h0 * w0.w;
            a0[4] += h0 * w1.x; a0[5] += h0 * w1.y; a0[6] += h0 * w1.z; a0[7] += h0 * w1.w;
            a1[0] += h1 * w0.x; a1[1] += h1 * w0.y; a1[2] += h1 * w0.z; a1[3] += h1 * w0.w;
            a1[4] += h1 * w1.x; a1[5] += h1 * w1.y; a1[6] += h1 * w1.z; a1[7] += h1 * w1.w;
            a2[0] += h2 * w0.x; a2[1] += h2 * w0.y; a2[2] += h2 * w0.z; a2[3] += h2 * w0.w;
            a2[4] += h2 * w1.x; a2[5] += h2 * w1.y; a2[6] += h2 * w1.z; a2[7] += h2 * w1.w;
            a3[0] += h3 * w0.x; a3[1] += h3 * w0.y; a3[2] += h3 * w0.z; a3[3] += h3 * w0.w;
            a3[4] += h3 * w1.x; a3[5] += h3 * w1.y; a3[6] += h3 * w1.z; a3[7] += h3 * w1.w;
        }
        // bias + stats + store
#pragma unroll
        for (int j = 0; j < 8; j++) {
            float y0 = a0[j] + bb[j], y1 = a1[j] + bb[j];
            float y2 = a2[j] + bb[j], y3 = a3[j] + bb[j];
            a0[j] = y0; a1[j] = y1; a2[j] = y2; a3[j] = y3;
            lsum[j] += (y0 + y1) + (y2 + y3);
            lssq[j] += (y0 * y0 + y1 * y1) + (y2 * y2 + y3 * y3);
        }
        float* o0 = &sc_y[(e0 + es      ) * 128 + c0];
        float* o1 = &sc_y[(e0 + es + 32 ) * 128 + c0];
        float* o2 = &sc_y[(e0 + es + 64 ) * 128 + c0];
        float* o3 = &sc_y[(e0 + es + 96 ) * 128 + c0];
        *(float4*)(o0)     = make_float4(a0[0], a0[1], a0[2], a0[3]);
        *(float4*)(o0 + 4) = make_float4(a0[4], a0[5], a0[6], a0[7]);
        *(float4*)(o1)     = make_float4(a1[0], a1[1], a1[2], a1[3]);
        *(float4*)(o1 + 4) = make_float4(a1[4], a1[5], a1[6], a1[7]);
        *(float4*)(o2)     = make_float4(a2[0], a2[1], a2[2], a2[3]);
        *(float4*)(o2 + 4) = make_float4(a2[4], a2[5], a2[6], a2[7]);
        *(float4*)(o3)     = make_float4(a3[0], a3[1], a3[2], a3[3]);
        *(float4*)(o3 + 4) = make_float4(a3[4], a3[5], a3[6], a3[7]);
    }

    // block-reduce stats (reuse hsh: need 32*128 = 4096 floats)
    __syncthreads();
    float* red = hsh;
#pragma unroll
    for (int j = 0; j < 8; j++) red[es * 128 + c0 + j] = lsum[j];
    __syncthreads();
    if (t < 128) {
        float s = 0.0f;
        for (int q = 0; q < 32; q++) s += red[q * 128 + t];
        atomicAdd(&sc_sum[t], s);
    }
    __syncthreads();
#pragma unroll
    for (int j = 0; j < 8; j++) red[es * 128 + c0 + j] = lssq[j];
    __syncthreads();
    if (t < 128) {
        float s = 0.0f;
        for (int q = 0; q < 32; q++) s += red[q * 128 + t];
        atomicAdd(&sc_ssq[t], s);
    }
}

// ---------------- apply edge BN + gate, scatter to agg (v4 red) ----------------
__global__ void edge_apply_kernel(const int* __restrict__ dst) {
    int idx = blockIdx.x * blockDim.x + threadIdx.x;
    if (idx >= N_EDGES * 16) return;
    int q = idx & 15;           // which group of 4 cols
    int e = idx >> 4;
    int c = q * 4;
    float4 ym = *(const float4*)&sc_y[e * 128 + c];
    float4 ys = *(const float4*)&sc_y[e * 128 + 64 + c];
    float4 r;
    {
        float m = sigmoid_f(ym.x * sc_scale[c + 0] + sc_shift[c + 0]);
        float s = softplus_f(ys.x * sc_scale[64 + c + 0] + sc_shift[64 + c + 0]);
        r.x = m * s;
    }
    {
        float m = sigmoid_f(ym.y * sc_scale[c + 1] + sc_shift[c + 1]);
        float s = softplus_f(ys.y * sc_scale[64 + c + 1] + sc_shift[64 + c + 1]);
        r.y = m * s;
    }
    {
        float m = sigmoid_f(ym.z * sc_scale[c + 2] + sc_shift[c + 2]);
        float s = softplus_f(ys.z * sc_scale[64 + c + 2] + sc_shift[64 + c + 2]);
        r.z = m * s;
    }
    {
        float m = sigmoid_f(ym.w * sc_scale[c + 3] + sc_shift[c + 3]);
        float s = softplus_f(ys.w * sc_scale[64 + c + 3] + sc_shift[64 + c + 3]);
        r.w = m * s;
    }
    red_v4(&sc_agg[dst[e] * D + c], r);
}

// ---------------- column stats of agg ----------------
__global__ __launch_bounds__(256) void node_stats_kernel() {
    __shared__ float red[256];
    int t = threadIdx.x;
    int c = t & 63, rs = t >> 6;
    float ls = 0.0f, lq = 0.0f;
    const int ntiles = N_NODES / 4;
    for (int ti = blockIdx.x; ti < ntiles; ti += gridDim.x) {
        float y = sc_agg[(ti * 4 + rs) * D + c];
        ls += y; lq += y * y;
    }
    red[t] = ls; __syncthreads();
    if (t < 64) atomicAdd(&sc_sum[t], red[t] + red[t + 64] + red[t + 128] + red[t + 192]);
    __syncthreads();
    red[t] = lq; __syncthreads();
    if (t < 64) atomicAdd(&sc_ssq[t], red[t] + red[t + 64] + red[t + 128] + red[t + 192]);
}

// v = softplus(bn(agg) + v)
__global__ void node_apply_kernel() {
    int idx = blockIdx.x * blockDim.x + threadIdx.x;
    if (idx < N_NODES * D) {
        int c = idx & 63;
        float x = sc_agg[idx] * sc_scale[c] + sc_shift[c] + sc_v[idx];
        sc_v[idx] = softplus_f(x);
    }
}

// ---------------- graph average pooling (v4 red) ----------------
__global__ void pool_kernel(const int* __restrict__ gid) {
    int idx = blockIdx.x * blockDim.x + threadIdx.x;
    if (idx >= N_NODES * 16) return;
    int q = idx & 15;
    int n = idx >> 4;
    int c = q * 4;
    int g = gid[n];
    float4 v = *(const float4*)&sc_v[n * D + c];
    red_v4(&sc_pool[g * D + c], v);
    if (q == 0) atomicAdd(&sc_cnt[g], 1.0f);
}
__global__ void pool_finish_kernel() {
    int idx = blockIdx.x * blockDim.x + threadIdx.x;
    if (idx < NG * D) {
        int g = idx >> 6;
        sc_pool[idx] /= fmaxf(sc_cnt[g], 1.0f);
    }
}

// ---------------- fc + BN + silu + regression head ----------------
__global__ __launch_bounds__(128) void fc_kernel(const float* __restrict__ Wfc, const float* __restrict__ bfc,
                                                 const float* __restrict__ gfc, const float* __restrict__ befc,
                                                 const float* __restrict__ Wout, const float* __restrict__ bout,
                                                 float* __restrict__ out) {
    __shared__ float psh[NG * D];
    __shared__ float red[128];
    int c = threadIdx.x;
    for (int i = c; i < NG * D; i += 128) psh[i] = sc_pool[i];
    __syncthreads();
    float s = 0.0f, q = 0.0f;
    float bc = bfc[c];
    for (int g = 0; g < NG; g++) {
        float acc = bc;
#pragma unroll 8
        for (int k = 0; k < D; k++) acc += psh[g * D + k] * Wfc[k * HDIM + c];
        sc_fcbuf[g * HDIM + c] = acc;
        s += acc; q += acc * acc;
    }
    float mu = s / (float)NG;
    float var = fmaxf(q / (float)NG - mu * mu, 0.0f);
    float sc = gfc[c] * rsqrtf(var + BN_EPS);
    float sh = befc[c] - mu * sc;
    float wo = Wout[c];
    float b0 = bout[0];
    for (int g = 0; g < NG; g++) {
        float y = sc_fcbuf[g * HDIM + c] * sc + sh;
        float val = y * sigmoid_f(y) * wo;
        red[c] = val; __syncthreads();
        for (int st = 64; st > 0; st >>= 1) {
            if (c < st) red[c] += red[c + st];
            __syncthreads();
        }
        if (c == 0) out[g] = red[0] + b0;
        __syncthreads();
    }
}

// ---------------- host launch ----------------
extern "C" void kernel_launch(void* const* d_in, const int* in_sizes, int n_in,
                              void* d_out, int out_size) {
    const float* node_feats = (const float*)d_in[0];
    const float* edge_feats = (const float*)d_in[1];
    const int*   src        = (const int*)d_in[2];
    const int*   dst        = (const int*)d_in[3];
    const int*   gid        = (const int*)d_in[4];
    const float* W_emb  = (const float*)d_in[5];
    const float* b_emb  = (const float*)d_in[6];
    const float* g_emb  = (const float*)d_in[7];
    const float* be_emb = (const float*)d_in[8];
    const float* conv_Wm  = (const float*)d_in[9];
    const float* conv_bm  = (const float*)d_in[10];
    const float* conv_gm  = (const float*)d_in[11];
    const float* conv_bem = (const float*)d_in[12];
    const float* conv_Ws  = (const float*)d_in[13];
    const float* conv_bs  = (const float*)d_in[14];
    const float* conv_gs  = (const float*)d_in[15];
    const float* conv_bes = (const float*)d_in[16];
    const float* conv_gn  = (const float*)d_in[17];
    const float* conv_ben = (const float*)d_in[18];
    const float* W_fc  = (const float*)d_in[19];
    const float* b_fc  = (const float*)d_in[20];
    const float* g_fc  = (const float*)d_in[21];
    const float* be_fc = (const float*)d_in[22];
    const float* W_out = (const float*)d_in[23];
    const float* b_out = (const float*)d_in[24];
    float* out = (float*)d_out;

    static int smem_set = 0;
    if (!smem_set) {
        cudaFuncSetAttribute(edge_gemm2_kernel, cudaFuncAttributeMaxDynamicSharedMemorySize, EG2_SMEM_BYTES);
        smem_set = 1;
    }

    const int ND = N_NODES * D;
    const int TB = 256;

    // embedding: v = silu(bn(x @ W_emb + b_emb))
    zero_stats_kernel<<<1, 128>>>();
    emb_kernel<<<512, 256>>>(node_feats, W_emb, b_emb);
    scale_kernel<<<1, 64>>>(g_emb, be_emb, (float)N_NODES, 0);
    silu_apply_kernel<<<(ND + TB - 1) / TB, TB>>>();

    for (int l = 0; l < NLAYERS; l++) {
        zero_stats_kernel<<<1, 128>>>();
        edge_gemm2_kernel<<<148, 512, EG2_SMEM_BYTES>>>(edge_feats, src, dst,
            conv_Wm + l * DIN * D, conv_bm + l * D,
            conv_Ws + l * DIN * D, conv_bs + l * D);
        scale_kernel<<<1, 64>>>(conv_gm + l * D, conv_bem + l * D, (float)N_EDGES, 0);
        scale_kernel<<<1, 64>>>(conv_gs + l * D, conv_bes + l * D, (float)N_EDGES, 64);
        zero_agg_kernel<<<(ND / 4 + TB - 1) / TB, TB>>>();
        edge_apply_kernel<<<(N_EDGES * 16 + TB - 1) / TB, TB>>>(dst);
        zero_stats_kernel<<<1, 128>>>();
        node_stats_kernel<<<256, 256>>>();
        scale_kernel<<<1, 64>>>(conv_gn + l * D, conv_ben + l * D, (float)N_NODES, 0);
        node_apply_kernel<<<(ND + TB - 1) / TB, TB>>>();
    }

    // pooling + fc + head
    zero_pool_kernel<<<(NG * D + TB - 1) / TB, TB>>>();
    pool_kernel<<<(N_NODES * 16 + TB - 1) / TB, TB>>>(gid);
    pool_finish_kernel<<<(NG * D + TB - 1) / TB, TB>>>();
    fc_kernel<<<1, 128>>>(W_fc, b_fc, g_fc, be_fc, W_out, b_out, out);
}

// round 4
// speedup vs baseline: 3.0782x; 1.8579x over previous
#include <cuda_runtime.h>
#include <cuda_bf16.h>
#include <math.h>
#include <stdint.h>

// ---------------- problem constants ----------------
#define N_NODES 50000
#define N_EDGES 800000
#define FN 92
#define FE 41
#define D 64
#define DIN 169
#define NG 100
#define HDIM 128
#define NLAYERS 3
#define BN_EPS 1e-5f

#define KPAD 176                  // 169 padded to 11 chunks of 16
#define EFP 48                    // padded edge-feature width (41 -> 48), covers k=128..175
#define NTILES (N_EDGES / 128)    // 6250

// smem geometry (bytes)
#define H_STRIDE 368              // 184 bf16 per row  (conflict-free ldmatrix)
#define W_STRIDE 272              // 136 bf16 per row  (conflict-free trans ldmatrix)
#define H_BUF (128 * H_STRIDE)    // 47104 per split
#define W_BUF (KPAD * W_STRIDE)   // 47872 per split
#define GEMM_DSMEM (2 * H_BUF + 2 * W_BUF)   // 189952

// ---------------- device scratch ----------------
__device__ float sc_v[N_NODES * D];
__device__ float sc_y[N_EDGES * 2 * D];
__device__ float sc_agg[N_NODES * D];
__device__ float sc_sum[2 * D];
__device__ float sc_ssq[2 * D];
__device__ float sc_scale[2 * D];
__device__ float sc_shift[2 * D];
__device__ float sc_pool[NG * D];
__device__ float sc_cnt[NG];
__device__ float sc_fcbuf[NG * HDIM];
__device__ __nv_bfloat16 sc_vh[N_NODES * D];
__device__ __nv_bfloat16 sc_vl[N_NODES * D];
__device__ __nv_bfloat16 sc_efh[N_EDGES * EFP];
__device__ __nv_bfloat16 sc_efl[N_EDGES * EFP];

// ---------------- math helpers ----------------
__device__ __forceinline__ float sigmoid_f(float x) { return 1.0f / (1.0f + __expf(-x)); }
__device__ __forceinline__ float softplus_f(float x) {
    return fmaxf(x, 0.0f) + log1pf(__expf(-fabsf(x)));
}
__device__ __forceinline__ void red_v4(float* p, float4 v) {
    asm volatile("red.global.add.v4.f32 [%0], {%1,%2,%3,%4};"
                 :: "l"(p), "f"(v.x), "f"(v.y), "f"(v.z), "f"(v.w) : "memory");
}
__device__ __forceinline__ uint32_t smem_u32(const void* p) {
    uint32_t a;
    asm("{ .reg .u64 t; cvta.to.shared.u64 t, %1; cvt.u32.u64 %0, t; }" : "=r"(a) : "l"(p));
    return a;
}
__device__ __forceinline__ void ldsm_x4(uint32_t addr, uint32_t* r) {
    asm volatile("ldmatrix.sync.aligned.m8n8.x4.shared.b16 {%0,%1,%2,%3}, [%4];"
                 : "=r"(r[0]), "=r"(r[1]), "=r"(r[2]), "=r"(r[3]) : "r"(addr));
}
__device__ __forceinline__ void ldsm_x4_t(uint32_t addr, uint32_t* r) {
    asm volatile("ldmatrix.sync.aligned.m8n8.x4.trans.shared.b16 {%0,%1,%2,%3}, [%4];"
                 : "=r"(r[0]), "=r"(r[1]), "=r"(r[2]), "=r"(r[3]) : "r"(addr));
}
__device__ __forceinline__ void mma_bf16(float* c, const uint32_t* a, uint32_t b0, uint32_t b1) {
    asm volatile("mma.sync.aligned.m16n8k16.row.col.f32.bf16.bf16.f32 "
                 "{%0,%1,%2,%3}, {%4,%5,%6,%7}, {%8,%9}, {%0,%1,%2,%3};"
                 : "+f"(c[0]), "+f"(c[1]), "+f"(c[2]), "+f"(c[3])
                 : "r"(a[0]), "r"(a[1]), "r"(a[2]), "r"(a[3]), "r"(b0), "r"(b1));
}

// ---------------- small kernels ----------------
__global__ void zero_stats_kernel() {
    int t = threadIdx.x;
    if (t < 2 * D) { sc_sum[t] = 0.0f; sc_ssq[t] = 0.0f; }
}
__global__ void zero_agg_kernel() {
    int i = blockIdx.x * blockDim.x + threadIdx.x;
    if (i < N_NODES * D / 4) ((float4*)sc_agg)[i] = make_float4(0.f, 0.f, 0.f, 0.f);
}
__global__ void zero_pool_kernel() {
    int i = blockIdx.x * blockDim.x + threadIdx.x;
    if (i < NG * D) sc_pool[i] = 0.0f;
    if (i < NG) sc_cnt[i] = 0.0f;
}
__global__ void scale_kernel(const float* __restrict__ gamma, const float* __restrict__ beta,
                             float count, int off) {
    int t = threadIdx.x;
    float mu = sc_sum[off + t] / count;
    float var = fmaxf(sc_ssq[off + t] / count - mu * mu, 0.0f);
    float s = gamma[t] * rsqrtf(var + BN_EPS);
    sc_scale[off + t] = s;
    sc_shift[off + t] = beta[t] - mu * s;
}

// split fp32 -> bf16 hi/lo
__global__ void vconv_kernel() {
    int i = blockIdx.x * blockDim.x + threadIdx.x;
    if (i < N_NODES * D) {
        float x = sc_v[i];
        __nv_bfloat16 h = __float2bfloat16(x);
        sc_vh[i] = h;
        sc_vl[i] = __float2bfloat16(x - __bfloat162float(h));
    }
}
__global__ void efconv_kernel(const float* __restrict__ ef) {
    int i = blockIdx.x * blockDim.x + threadIdx.x;
    if (i >= N_EDGES * EFP) return;
    int e = i / EFP, j = i - e * EFP;
    float x = (j < FE) ? ef[(size_t)e * FE + j] : 0.0f;
    __nv_bfloat16 h = __float2bfloat16(x);
    sc_efh[i] = h;
    sc_efl[i] = __float2bfloat16(x - __bfloat162float(h));
}

// ---------------- node embedding GEMM (fp32, small) ----------------
__global__ __launch_bounds__(256) void emb_kernel(const float* __restrict__ x,
                                                  const float* __restrict__ W,
                                                  const float* __restrict__ b) {
    __shared__ float Wsh[FN * D];
    __shared__ float xsh[4][FN];
    __shared__ float red[256];
    int t = threadIdx.x;
    for (int i = t; i < FN * D; i += 256) Wsh[i] = W[i];
    int c = t & 63, rs = t >> 6;
    float bc = b[c];
    float ls = 0.0f, lq = 0.0f;
    const int ntiles = N_NODES / 4;
    for (int ti = blockIdx.x; ti < ntiles; ti += gridDim.x) {
        int r0 = ti * 4;
        __syncthreads();
        for (int i = t; i < 4 * FN; i += 256) {
            int rr = i / FN, k = i - rr * FN;
            xsh[rr][k] = x[(r0 + rr) * FN + k];
        }
        __syncthreads();
        float acc = bc;
#pragma unroll 4
        for (int k = 0; k < FN; k++) acc += xsh[rs][k] * Wsh[k * D + c];
        sc_v[(r0 + rs) * D + c] = acc;
        ls += acc; lq += acc * acc;
    }
    __syncthreads();
    red[t] = ls; __syncthreads();
    if (t < 64) atomicAdd(&sc_sum[t], red[t] + red[t + 64] + red[t + 128] + red[t + 192]);
    __syncthreads();
    red[t] = lq; __syncthreads();
    if (t < 64) atomicAdd(&sc_ssq[t], red[t] + red[t + 64] + red[t + 128] + red[t + 192]);
}

__global__ void silu_apply_kernel() {
    int idx = blockIdx.x * blockDim.x + threadIdx.x;
    if (idx < N_NODES * D) {
        int c = idx & 63;
        float y = sc_v[idx] * sc_scale[c] + sc_shift[c];
        sc_v[idx] = y * sigmoid_f(y);
    }
}

// ---------------- HMMA edge GEMM ----------------
// y[e][0..127] = h[e] @ [Wm|Ws] + bias, 3-term bf16 split for fp32 accuracy.
// Tile: 128 edges x 128 cols. 512 threads = 16 warps: warp = (eg 0..7) x (ch 0..1),
// covering edges eg*16..+15, cols ch*64..+63 (8 n-tiles of m16n8k16).
__global__ __launch_bounds__(512, 1) void edge_gemm_mma(const int* __restrict__ src,
                                                        const int* __restrict__ dst,
                                                        const float* __restrict__ Wm,
                                                        const float* __restrict__ bm,
                                                        const float* __restrict__ Ws,
                                                        const float* __restrict__ bs) {
    extern __shared__ char smb[];
    char* h_hi = smb;
    char* h_lo = smb + H_BUF;
    char* w_hi = smb + 2 * H_BUF;
    char* w_lo = smb + 2 * H_BUF + W_BUF;
    __shared__ int ssrc[128], sdst[128];
    __shared__ float sred[128], qred[128];

    int t = threadIdx.x;
    int lane = t & 31;
    int wid = t >> 5;
    int eg = wid & 7;          // edge group (16 edges)
    int ch = wid >> 3;         // column half (64 cols)

    uint32_t h_hi_u = smem_u32(h_hi);
    uint32_t h_lo_u = smem_u32(h_lo);
    uint32_t w_hi_u = smem_u32(w_hi);
    uint32_t w_lo_u = smem_u32(w_lo);

    if (t < 128) { sred[t] = 0.0f; qred[t] = 0.0f; }

    // prezero W buffers (rows 169..175 must be 0)
    for (int i = t; i < 2 * W_BUF / 16; i += 512)
        ((uint4*)w_hi)[i] = make_uint4(0, 0, 0, 0);
    __syncthreads();

    // stage W hi/lo: W[k][c], c<64 from Wm, else Ws
    for (int i = t; i < DIN * 128; i += 512) {
        int c = i & 127, k = i >> 7;
        float wv = (c < 64) ? Wm[k * 64 + c] : Ws[k * 64 + (c - 64)];
        __nv_bfloat16 hi = __float2bfloat16(wv);
        __nv_bfloat16 lo = __float2bfloat16(wv - __bfloat162float(hi));
        uint32_t byte = (uint32_t)k * W_STRIDE + (uint32_t)c * 2;
        *(__nv_bfloat16*)(w_hi + byte) = hi;
        *(__nv_bfloat16*)(w_lo + byte) = lo;
    }

    // per-thread bias for its 16 columns: col = ch*64 + j*8 + (lane&3)*2 + s
    float bias0[8], bias1[8];
#pragma unroll
    for (int j = 0; j < 8; j++) {
        int c = ch * 64 + j * 8 + (lane & 3) * 2;
        bias0[j] = (c < 64) ? bm[c] : bs[c - 64];
        bias1[j] = (c + 1 < 64) ? bm[c + 1] : bs[c + 1 - 64];
    }
    float colsum0[8], colsum1[8], colssq0[8], colssq1[8];
#pragma unroll
    for (int j = 0; j < 8; j++) { colsum0[j] = colsum1[j] = colssq0[j] = colssq1[j] = 0.0f; }

    // A ldmatrix address components (within h buffer)
    uint32_t a_row = (uint32_t)(eg * 16 + (lane & 15)) * H_STRIDE;
    uint32_t a_kof = (uint32_t)(lane >> 4) * 16;   // (lane>>4)*8 bf16 = 16 bytes
    // B ldmatrix address components (within w buffer)
    uint32_t b_krow = (uint32_t)((lane & 7) + ((lane >> 3) & 1) * 8) * W_STRIDE;
    uint32_t b_col = (uint32_t)(ch * 64 + (lane >> 4) * 8) * 2;

    for (int ti = blockIdx.x; ti < NTILES; ti += gridDim.x) {
        int e0 = ti * 128;
        __syncthreads();
        if (t < 128) ssrc[t] = src[e0 + t];
        else if (t < 256) sdst[t - 128] = dst[e0 + t - 128];
        __syncthreads();

        // stage h tiles: 22 slots x 2 splits x 128 rows of 16B
        for (int i = t; i < 44 * 128; i += 512) {
            int slot = i >> 7, row = i & 127;
            int lobuf = slot >= 22;
            int s0 = lobuf ? slot - 22 : slot;
            const uint4* gp;
            uint32_t k0;
            if (s0 < 8) {
                const __nv_bfloat16* va = lobuf ? sc_vl : sc_vh;
                gp = (const uint4*)(va + ssrc[row] * D) + s0;
                k0 = (uint32_t)s0 * 8;
            } else if (s0 < 16) {
                const __nv_bfloat16* va = lobuf ? sc_vl : sc_vh;
                gp = (const uint4*)(va + sdst[row] * D) + (s0 - 8);
                k0 = 64 + (uint32_t)(s0 - 8) * 8;
            } else {
                const __nv_bfloat16* ea = lobuf ? sc_efl : sc_efh;
                gp = (const uint4*)(ea + (size_t)(e0 + row) * EFP) + (s0 - 16);
                k0 = 128 + (uint32_t)(s0 - 16) * 8;
            }
            uint4 val = *gp;
            *(uint4*)((lobuf ? h_lo : h_hi) + (uint32_t)row * H_STRIDE + k0 * 2) = val;
        }
        __syncthreads();

        float acc[8][4];
#pragma unroll
        for (int j = 0; j < 8; j++) { acc[j][0] = acc[j][1] = acc[j][2] = acc[j][3] = 0.0f; }

        // 3 splits x 11 k-chunks
#pragma unroll
        for (int s = 0; s < 3; s++) {
            uint32_t ha = (s == 2) ? h_lo_u : h_hi_u;
            uint32_t wa = (s == 1) ? w_lo_u : w_hi_u;
            for (int kc = 0; kc < 11; kc++) {
                uint32_t a[4];
                ldsm_x4(ha + a_row + (uint32_t)kc * 32 + a_kof, a);
#pragma unroll
                for (int jp = 0; jp < 4; jp++) {
                    uint32_t b[4];
                    ldsm_x4_t(wa + (uint32_t)kc * 16 * W_STRIDE + b_krow + b_col + (uint32_t)jp * 32, b);
                    mma_bf16(acc[2 * jp], a, b[0], b[1]);
                    mma_bf16(acc[2 * jp + 1], a, b[2], b[3]);
                }
            }
        }

        // epilogue: bias + stats + store
        int r0 = e0 + eg * 16 + (lane >> 2);
        int cb = ch * 64 + (lane & 3) * 2;
#pragma unroll
        for (int j = 0; j < 8; j++) {
            float y0 = acc[j][0] + bias0[j];
            float y1 = acc[j][1] + bias1[j];
            float y2 = acc[j][2] + bias0[j];
            float y3 = acc[j][3] + bias1[j];
            colsum0[j] += y0 + y2; colsum1[j] += y1 + y3;
            colssq0[j] += y0 * y0 + y2 * y2; colssq1[j] += y1 * y1 + y3 * y3;
            int c = cb + j * 8;
            *(float2*)&sc_y[(size_t)r0 * 128 + c] = make_float2(y0, y1);
            *(float2*)&sc_y[(size_t)(r0 + 8) * 128 + c] = make_float2(y2, y3);
        }
    }

    // reduce stats: smem atomics then global
    __syncthreads();
#pragma unroll
    for (int j = 0; j < 8; j++) {
        int c = ch * 64 + j * 8 + (lane & 3) * 2;
        atomicAdd(&sred[c], colsum0[j]);
        atomicAdd(&sred[c + 1], colsum1[j]);
        atomicAdd(&qred[c], colssq0[j]);
        atomicAdd(&qred[c + 1], colssq1[j]);
    }
    __syncthreads();
    if (t < 128) {
        atomicAdd(&sc_sum[t], sred[t]);
        atomicAdd(&sc_ssq[t], qred[t]);
    }
}

// ---------------- apply edge BN + gate, scatter to agg (v4 red) ----------------
__global__ void edge_apply_kernel(const int* __restrict__ dst) {
    int idx = blockIdx.x * blockDim.x + threadIdx.x;
    if (idx >= N_EDGES * 16) return;
    int q = idx & 15;
    int e = idx >> 4;
    int c = q * 4;
    float4 ym = *(const float4*)&sc_y[(size_t)e * 128 + c];
    float4 ys = *(const float4*)&sc_y[(size_t)e * 128 + 64 + c];
    float4 r;
    r.x = sigmoid_f(ym.x * sc_scale[c+0] + sc_shift[c+0]) * softplus_f(ys.x * sc_scale[64+c+0] + sc_shift[64+c+0]);
    r.y = sigmoid_f(ym.y * sc_scale[c+1] + sc_shift[c+1]) * softplus_f(ys.y * sc_scale[64+c+1] + sc_shift[64+c+1]);
    r.z = sigmoid_f(ym.z * sc_scale[c+2] + sc_shift[c+2]) * softplus_f(ys.z * sc_scale[64+c+2] + sc_shift[64+c+2]);
    r.w = sigmoid_f(ym.w * sc_scale[c+3] + sc_shift[c+3]) * softplus_f(ys.w * sc_scale[64+c+3] + sc_shift[64+c+3]);
    red_v4(&sc_agg[dst[e] * D + c], r);
}

__global__ __launch_bounds__(256) void node_stats_kernel() {
    __shared__ float red[256];
    int t = threadIdx.x;
    int c = t & 63, rs = t >> 6;
    float ls = 0.0f, lq = 0.0f;
    const int ntiles = N_NODES / 4;
    for (int ti = blockIdx.x; ti < ntiles; ti += gridDim.x) {
        float y = sc_agg[(ti * 4 + rs) * D + c];
        ls += y; lq += y * y;
    }
    red[t] = ls; __syncthreads();
    if (t < 64) atomicAdd(&sc_sum[t], red[t] + red[t + 64] + red[t + 128] + red[t + 192]);
    __syncthreads();
    red[t] = lq; __syncthreads();
    if (t < 64) atomicAdd(&sc_ssq[t], red[t] + red[t + 64] + red[t + 128] + red[t + 192]);
}

__global__ void node_apply_kernel() {
    int idx = blockIdx.x * blockDim.x + threadIdx.x;
    if (idx < N_NODES * D) {
        int c = idx & 63;
        float x = sc_agg[idx] * sc_scale[c] + sc_shift[c] + sc_v[idx];
        sc_v[idx] = softplus_f(x);
    }
}

__global__ void pool_kernel(const int* __restrict__ gid) {
    int idx = blockIdx.x * blockDim.x + threadIdx.x;
    if (idx >= N_NODES * 16) return;
    int q = idx & 15;
    int n = idx >> 4;
    int c = q * 4;
    int g = gid[n];
    float4 v = *(const float4*)&sc_v[n * D + c];
    red_v4(&sc_pool[g * D + c], v);
    if (q == 0) atomicAdd(&sc_cnt[g], 1.0f);
}
__global__ void pool_finish_kernel() {
    int idx = blockIdx.x * blockDim.x + threadIdx.x;
    if (idx < NG * D) {
        int g = idx >> 6;
        sc_pool[idx] /= fmaxf(sc_cnt[g], 1.0f);
    }
}

__global__ __launch_bounds__(128) void fc_kernel(const float* __restrict__ Wfc, const float* __restrict__ bfc,
                                                 const float* __restrict__ gfc, const float* __restrict__ befc,
                                                 const float* __restrict__ Wout, const float* __restrict__ bout,
                                                 float* __restrict__ out) {
    __shared__ float psh[NG * D];
    __shared__ float red[128];
    int c = threadIdx.x;
    for (int i = c; i < NG * D; i += 128) psh[i] = sc_pool[i];
    __syncthreads();
    float s = 0.0f, q = 0.0f;
    float bc = bfc[c];
    for (int g = 0; g < NG; g++) {
        float acc = bc;
#pragma unroll 8
        for (int k = 0; k < D; k++) acc += psh[g * D + k] * Wfc[k * HDIM + c];
        sc_fcbuf[g * HDIM + c] = acc;
        s += acc; q += acc * acc;
    }
    float mu = s / (float)NG;
    float var = fmaxf(q / (float)NG - mu * mu, 0.0f);
    float sc = gfc[c] * rsqrtf(var + BN_EPS);
    float sh = befc[c] - mu * sc;
    float wo = Wout[c];
    float b0 = bout[0];
    for (int g = 0; g < NG; g++) {
        float y = sc_fcbuf[g * HDIM + c] * sc + sh;
        float val = y * sigmoid_f(y) * wo;
        red[c] = val; __syncthreads();
        for (int st = 64; st > 0; st >>= 1) {
            if (c < st) red[c] += red[c + st];
            __syncthreads();
        }
        if (c == 0) out[g] = red[0] + b0;
        __syncthreads();
    }
}

// ---------------- host launch ----------------
extern "C" void kernel_launch(void* const* d_in, const int* in_sizes, int n_in,
                              void* d_out, int out_size) {
    const float* node_feats = (const float*)d_in[0];
    const float* edge_feats = (const float*)d_in[1];
    const int*   src        = (const int*)d_in[2];
    const int*   dst        = (const int*)d_in[3];
    const int*   gid        = (const int*)d_in[4];
    const float* W_emb  = (const float*)d_in[5];
    const float* b_emb  = (const float*)d_in[6];
    const float* g_emb  = (const float*)d_in[7];
    const float* be_emb = (const float*)d_in[8];
    const float* conv_Wm  = (const float*)d_in[9];
    const float* conv_bm  = (const float*)d_in[10];
    const float* conv_gm  = (const float*)d_in[11];
    const float* conv_bem = (const float*)d_in[12];
    const float* conv_Ws  = (const float*)d_in[13];
    const float* conv_bs  = (const float*)d_in[14];
    const float* conv_gs  = (const float*)d_in[15];
    const float* conv_bes = (const float*)d_in[16];
    const float* conv_gn  = (const float*)d_in[17];
    const float* conv_ben = (const float*)d_in[18];
    const float* W_fc  = (const float*)d_in[19];
    const float* b_fc  = (const float*)d_in[20];
    const float* g_fc  = (const float*)d_in[21];
    const float* be_fc = (const float*)d_in[22];
    const float* W_out = (const float*)d_in[23];
    const float* b_out = (const float*)d_in[24];
    float* out = (float*)d_out;

    cudaFuncSetAttribute(edge_gemm_mma, cudaFuncAttributeMaxDynamicSharedMemorySize, GEMM_DSMEM);

    const int ND = N_NODES * D;
    const int TB = 256;

    // edge feature split (constant across layers)
    efconv_kernel<<<(N_EDGES * EFP + TB - 1) / TB, TB>>>(edge_feats);

    // embedding: v = silu(bn(x @ W_emb + b_emb))
    zero_stats_kernel<<<1, 128>>>();
    emb_kernel<<<512, 256>>>(node_feats, W_emb, b_emb);
    scale_kernel<<<1, 64>>>(g_emb, be_emb, (float)N_NODES, 0);
    silu_apply_kernel<<<(ND + TB - 1) / TB, TB>>>();

    for (int l = 0; l < NLAYERS; l++) {
        vconv_kernel<<<(ND + TB - 1) / TB, TB>>>();
        zero_stats_kernel<<<1, 128>>>();
        edge_gemm_mma<<<148, 512, GEMM_DSMEM>>>(src, dst,
            conv_Wm + l * DIN * D, conv_bm + l * D,
            conv_Ws + l * DIN * D, conv_bs + l * D);
        scale_kernel<<<1, 64>>>(conv_gm + l * D, conv_bem + l * D, (float)N_EDGES, 0);
        scale_kernel<<<1, 64>>>(conv_gs + l * D, conv_bes + l * D, (float)N_EDGES, 64);
        zero_agg_kernel<<<(ND / 4 + TB - 1) / TB, TB>>>();
        edge_apply_kernel<<<(N_EDGES * 16 + TB - 1) / TB, TB>>>(dst);
        zero_stats_kernel<<<1, 128>>>();
        node_stats_kernel<<<256, 256>>>();
        scale_kernel<<<1, 64>>>(conv_gn + l * D, conv_ben + l * D, (float)N_NODES, 0);
        node_apply_kernel<<<(ND + TB - 1) / TB, TB>>>();
    }

    zero_pool_kernel<<<(NG * D + TB - 1) / TB, TB>>>();
    pool_kernel<<<(N_NODES * 16 + TB - 1) / TB, TB>>>(gid);
    pool_finish_kernel<<<(NG * D + TB - 1) / TB, TB>>>();
    fc_kernel<<<1, 128>>>(W_fc, b_fc, g_fc, be_fc, W_out, b_out, out);
}

// round 5
// speedup vs baseline: 4.4679x; 1.4515x over previous
#include <cuda_runtime.h>
#include <cuda_bf16.h>
#include <math.h>
#include <stdint.h>

// ---------------- problem constants ----------------
#define N_NODES 50000
#define N_EDGES 800000
#define FN 92
#define FE 41
#define D 64
#define DIN 169
#define NG 100
#define HDIM 128
#define NLAYERS 3
#define BN_EPS 1e-5f

#define KPAD 176                  // 169 padded to 11 chunks of 16
#define EFP 48                    // padded edge-feature width (41 -> 48)
#define TEDGE 64                  // edges per tile
#define NTILES (N_EDGES / TEDGE)  // 12500

// smem geometry (bytes)
#define H_STRIDE 368              // 184 bf16 per row (conflict-free ldmatrix)
#define W_STRIDE 272              // 136 bf16 per row (conflict-free trans ldmatrix)
#define HBUF_B (TEDGE * H_STRIDE) // 23552 per split per stage
#define W_BUF (KPAD * W_STRIDE)   // 47872 per split
#define GEMM_DSMEM (4 * HBUF_B + 2 * W_BUF)   // 94208 + 95744 = 189952

// ---------------- device scratch ----------------
__device__ float sc_v[N_NODES * D];
__device__ float sc_y[N_EDGES * 2 * D];
__device__ float sc_agg[N_NODES * D];
__device__ float sc_sum[2 * D];
__device__ float sc_ssq[2 * D];
__device__ float sc_scale[2 * D];
__device__ float sc_shift[2 * D];
__device__ float sc_pool[NG * D];
__device__ float sc_cnt[NG];
__device__ float sc_fcbuf[NG * HDIM];
__device__ __nv_bfloat16 sc_vh[N_NODES * D];
__device__ __nv_bfloat16 sc_vl[N_NODES * D];
__device__ __nv_bfloat16 sc_efh[N_EDGES * EFP];
__device__ __nv_bfloat16 sc_efl[N_EDGES * EFP];

// ---------------- math helpers ----------------
__device__ __forceinline__ float sigmoid_f(float x) { return 1.0f / (1.0f + __expf(-x)); }
__device__ __forceinline__ float softplus_f(float x) {
    return fmaxf(x, 0.0f) + log1pf(__expf(-fabsf(x)));
}
__device__ __forceinline__ void red_v4(float* p, float4 v) {
    asm volatile("red.global.add.v4.f32 [%0], {%1,%2,%3,%4};"
                 :: "l"(p), "f"(v.x), "f"(v.y), "f"(v.z), "f"(v.w) : "memory");
}
__device__ __forceinline__ uint32_t smem_u32(const void* p) {
    uint32_t a;
    asm("{ .reg .u64 t; cvta.to.shared.u64 t, %1; cvt.u32.u64 %0, t; }" : "=r"(a) : "l"(p));
    return a;
}
__device__ __forceinline__ void ldsm_x4(uint32_t addr, uint32_t* r) {
    asm volatile("ldmatrix.sync.aligned.m8n8.x4.shared.b16 {%0,%1,%2,%3}, [%4];"
                 : "=r"(r[0]), "=r"(r[1]), "=r"(r[2]), "=r"(r[3]) : "r"(addr));
}
__device__ __forceinline__ void ldsm_x4_t(uint32_t addr, uint32_t* r) {
    asm volatile("ldmatrix.sync.aligned.m8n8.x4.trans.shared.b16 {%0,%1,%2,%3}, [%4];"
                 : "=r"(r[0]), "=r"(r[1]), "=r"(r[2]), "=r"(r[3]) : "r"(addr));
}
__device__ __forceinline__ void mma_bf16(float* c, const uint32_t* a, uint32_t b0, uint32_t b1) {
    asm volatile("mma.sync.aligned.m16n8k16.row.col.f32.bf16.bf16.f32 "
                 "{%0,%1,%2,%3}, {%4,%5,%6,%7}, {%8,%9}, {%0,%1,%2,%3};"
                 : "+f"(c[0]), "+f"(c[1]), "+f"(c[2]), "+f"(c[3])
                 : "r"(a[0]), "r"(a[1]), "r"(a[2]), "r"(a[3]), "r"(b0), "r"(b1));
}
__device__ __forceinline__ void cpa16(uint32_t saddr, const void* g) {
    asm volatile("cp.async.ca.shared.global [%0], [%1], 16;" :: "r"(saddr), "l"(g));
}
#define CP_COMMIT() asm volatile("cp.async.commit_group;" ::: "memory")
#define CP_WAIT(n)  asm volatile("cp.async.wait_group %0;" :: "n"(n) : "memory")

// ---------------- small kernels ----------------
__global__ void zero_stats_kernel() {
    int t = threadIdx.x;
    if (t < 2 * D) { sc_sum[t] = 0.0f; sc_ssq[t] = 0.0f; }
}
__global__ void zero_agg_kernel() {
    int i = blockIdx.x * blockDim.x + threadIdx.x;
    if (i < N_NODES * D / 4) ((float4*)sc_agg)[i] = make_float4(0.f, 0.f, 0.f, 0.f);
}
__global__ void zero_pool_kernel() {
    int i = blockIdx.x * blockDim.x + threadIdx.x;
    if (i < NG * D) sc_pool[i] = 0.0f;
    if (i < NG) sc_cnt[i] = 0.0f;
}
__global__ void scale_kernel(const float* __restrict__ gamma, const float* __restrict__ beta,
                             float count, int off) {
    int t = threadIdx.x;
    float mu = sc_sum[off + t] / count;
    float var = fmaxf(sc_ssq[off + t] / count - mu * mu, 0.0f);
    float s = gamma[t] * rsqrtf(var + BN_EPS);
    sc_scale[off + t] = s;
    sc_shift[off + t] = beta[t] - mu * s;
}

// split fp32 -> bf16 hi/lo
__global__ void vconv_kernel() {
    int i = blockIdx.x * blockDim.x + threadIdx.x;
    if (i < N_NODES * D) {
        float x = sc_v[i];
        __nv_bfloat16 h = __float2bfloat16(x);
        sc_vh[i] = h;
        sc_vl[i] = __float2bfloat16(x - __bfloat162float(h));
    }
}
__global__ void efconv_kernel(const float* __restrict__ ef) {
    int i = blockIdx.x * blockDim.x + threadIdx.x;
    if (i >= N_EDGES * EFP) return;
    int e = i / EFP, j = i - e * EFP;
    float x = (j < FE) ? ef[(size_t)e * FE + j] : 0.0f;
    __nv_bfloat16 h = __float2bfloat16(x);
    sc_efh[i] = h;
    sc_efl[i] = __float2bfloat16(x - __bfloat162float(h));
}

// ---------------- node embedding GEMM (fp32, small) ----------------
__global__ __launch_bounds__(256) void emb_kernel(const float* __restrict__ x,
                                                  const float* __restrict__ W,
                                                  const float* __restrict__ b) {
    __shared__ float Wsh[FN * D];
    __shared__ float xsh[4][FN];
    __shared__ float red[256];
    int t = threadIdx.x;
    for (int i = t; i < FN * D; i += 256) Wsh[i] = W[i];
    int c = t & 63, rs = t >> 6;
    float bc = b[c];
    float ls = 0.0f, lq = 0.0f;
    const int ntiles = N_NODES / 4;
    for (int ti = blockIdx.x; ti < ntiles; ti += gridDim.x) {
        int r0 = ti * 4;
        __syncthreads();
        for (int i = t; i < 4 * FN; i += 256) {
            int rr = i / FN, k = i - rr * FN;
            xsh[rr][k] = x[(r0 + rr) * FN + k];
        }
        __syncthreads();
        float acc = bc;
#pragma unroll 4
        for (int k = 0; k < FN; k++) acc += xsh[rs][k] * Wsh[k * D + c];
        sc_v[(r0 + rs) * D + c] = acc;
        ls += acc; lq += acc * acc;
    }
    __syncthreads();
    red[t] = ls; __syncthreads();
    if (t < 64) atomicAdd(&sc_sum[t], red[t] + red[t + 64] + red[t + 128] + red[t + 192]);
    __syncthreads();
    red[t] = lq; __syncthreads();
    if (t < 64) atomicAdd(&sc_ssq[t], red[t] + red[t + 64] + red[t + 128] + red[t + 192]);
}

__global__ void silu_apply_kernel() {
    int idx = blockIdx.x * blockDim.x + threadIdx.x;
    if (idx < N_NODES * D) {
        int c = idx & 63;
        float y = sc_v[idx] * sc_scale[c] + sc_shift[c];
        sc_v[idx] = y * sigmoid_f(y);
    }
}

// ---------------- pipelined HMMA edge GEMM ----------------
// Tile: 64 edges x 128 cols, double-buffered h via cp.async.
// 16 warps = eg(0..3: 16 edges) x ch(0..3: 32 cols).
__device__ __forceinline__ void issue_h(uint32_t smb_u, int st, int e0,
                                        const int* ssrc, const int* sdst, int t) {
    uint32_t base_hi = smb_u + (uint32_t)(st * 2) * HBUF_B;
    uint32_t base_lo = base_hi + HBUF_B;
    for (int i = t; i < 44 * TEDGE; i += 512) {
        int slot = i >> 6, row = i & 63;
        int lobuf = slot >= 22;
        int s0 = lobuf ? slot - 22 : slot;
        const __nv_bfloat16* g;
        uint32_t k0;
        if (s0 < 8) {
            g = (lobuf ? sc_vl : sc_vh) + ssrc[row] * D + s0 * 8;
            k0 = (uint32_t)s0 * 8;
        } else if (s0 < 16) {
            g = (lobuf ? sc_vl : sc_vh) + sdst[row] * D + (s0 - 8) * 8;
            k0 = 64 + (uint32_t)(s0 - 8) * 8;
        } else {
            g = (lobuf ? sc_efl : sc_efh) + (size_t)(e0 + row) * EFP + (s0 - 16) * 8;
            k0 = 128 + (uint32_t)(s0 - 16) * 8;
        }
        cpa16((lobuf ? base_lo : base_hi) + (uint32_t)row * H_STRIDE + k0 * 2, g);
    }
}

__global__ __launch_bounds__(512, 1) void edge_gemm_mma(const int* __restrict__ src,
                                                        const int* __restrict__ dst,
                                                        const float* __restrict__ Wm,
                                                        const float* __restrict__ bm,
                                                        const float* __restrict__ Ws,
                                                        const float* __restrict__ bs) {
    extern __shared__ char smb[];
    uint32_t smb_u = smem_u32(smb);
    char* w_hi = smb + 4 * HBUF_B;
    char* w_lo = w_hi + W_BUF;
    uint32_t w_hi_u = smb_u + 4 * HBUF_B;
    uint32_t w_lo_u = w_hi_u + W_BUF;
    __shared__ int sidx[2][2][TEDGE];
    __shared__ float sred[128], qred[128];

    int t = threadIdx.x;
    int lane = t & 31;
    int wid = t >> 5;
    int eg = wid & 3;          // 16-edge group
    int ch = wid >> 2;         // 32-col group

    if (t < 128) { sred[t] = 0.0f; qred[t] = 0.0f; }

    // prezero W buffers (k rows 169..175 must be 0)
    for (int i = t; i < 2 * W_BUF / 16; i += 512)
        ((uint4*)w_hi)[i] = make_uint4(0, 0, 0, 0);
    __syncthreads();

    // stage W hi/lo
    for (int i = t; i < DIN * 128; i += 512) {
        int c = i & 127, k = i >> 7;
        float wv = (c < 64) ? Wm[k * 64 + c] : Ws[k * 64 + (c - 64)];
        __nv_bfloat16 hi = __float2bfloat16(wv);
        __nv_bfloat16 lo = __float2bfloat16(wv - __bfloat162float(hi));
        uint32_t byte = (uint32_t)k * W_STRIDE + (uint32_t)c * 2;
        *(__nv_bfloat16*)(w_hi + byte) = hi;
        *(__nv_bfloat16*)(w_lo + byte) = lo;
    }

    // per-thread bias: cols c = ch*32 + jn*8 + (lane&3)*2 (+1)
    float bias0[4], bias1[4];
#pragma unroll
    for (int jn = 0; jn < 4; jn++) {
        int c = ch * 32 + jn * 8 + (lane & 3) * 2;
        bias0[jn] = (c < 64) ? bm[c] : bs[c - 64];
        bias1[jn] = (c + 1 < 64) ? bm[c + 1] : bs[c + 1 - 64];
    }
    float cs0[4], cs1[4], cq0[4], cq1[4];
#pragma unroll
    for (int jn = 0; jn < 4; jn++) { cs0[jn] = cs1[jn] = cq0[jn] = cq1[jn] = 0.0f; }

    // fragment address components
    uint32_t a_off = (uint32_t)(eg * 16 + (lane & 15)) * H_STRIDE + (uint32_t)(lane >> 4) * 16;
    uint32_t b_off = (uint32_t)((lane & 7) + ((lane >> 3) & 1) * 8) * W_STRIDE +
                     (uint32_t)(ch * 32 + (lane >> 4) * 8) * 2;

    const int GRID = gridDim.x;
    int ti0 = blockIdx.x;

    // prologue: indices + cp.async for first tile
    if (t < 64) sidx[0][0][t] = src[ti0 * TEDGE + t];
    else if (t < 128) sidx[0][1][t - 64] = dst[ti0 * TEDGE + t - 64];
    __syncthreads();                       // W staged + idx visible
    issue_h(smb_u, 0, ti0 * TEDGE, sidx[0][0], sidx[0][1], t);
    CP_COMMIT();

    int stage = 0;
    for (int ti = ti0; ti < NTILES; ti += GRID) {
        int tn = ti + GRID;
        if (tn < NTILES) {
            __syncthreads();               // buf[stage^1] + sidx[stage^1] free
            if (t < 64) sidx[stage ^ 1][0][t] = src[tn * TEDGE + t];
            else if (t < 128) sidx[stage ^ 1][1][t - 64] = dst[tn * TEDGE + t - 64];
            __syncthreads();
            issue_h(smb_u, stage ^ 1, tn * TEDGE, sidx[stage ^ 1][0], sidx[stage ^ 1][1], t);
            CP_COMMIT();
            CP_WAIT(1);                    // tile ti's group done
        } else {
            CP_WAIT(0);
        }
        __syncthreads();

        uint32_t hb_hi = smb_u + (uint32_t)(stage * 2) * HBUF_B + a_off;
        uint32_t hb_lo = hb_hi + HBUF_B;

        float acc[4][4];
#pragma unroll
        for (int jn = 0; jn < 4; jn++) { acc[jn][0] = acc[jn][1] = acc[jn][2] = acc[jn][3] = 0.0f; }

#pragma unroll
        for (int kc = 0; kc < 11; kc++) {
            uint32_t ah[4], al[4];
            ldsm_x4(hb_hi + (uint32_t)kc * 32, ah);
            ldsm_x4(hb_lo + (uint32_t)kc * 32, al);
#pragma unroll
            for (int jp = 0; jp < 2; jp++) {
                uint32_t bh[4], bl[4];
                uint32_t boff = (uint32_t)kc * 16 * W_STRIDE + b_off + (uint32_t)jp * 32;
                ldsm_x4_t(w_hi_u + boff, bh);
                ldsm_x4_t(w_lo_u + boff, bl);
                mma_bf16(acc[2 * jp],     ah, bh[0], bh[1]);
                mma_bf16(acc[2 * jp + 1], ah, bh[2], bh[3]);
                mma_bf16(acc[2 * jp],     al, bh[0], bh[1]);
                mma_bf16(acc[2 * jp + 1], al, bh[2], bh[3]);
                mma_bf16(acc[2 * jp],     ah, bl[0], bl[1]);
                mma_bf16(acc[2 * jp + 1], ah, bl[2], bl[3]);
            }
        }

        // epilogue: bias + stats + store
        int r0 = ti * TEDGE + eg * 16 + (lane >> 2);
#pragma unroll
        for (int jn = 0; jn < 4; jn++) {
            int c = ch * 32 + jn * 8 + (lane & 3) * 2;
            float y0 = acc[jn][0] + bias0[jn];
            float y1 = acc[jn][1] + bias1[jn];
            float y2 = acc[jn][2] + bias0[jn];
            float y3 = acc[jn][3] + bias1[jn];
            cs0[jn] += y0 + y2; cs1[jn] += y1 + y3;
            cq0[jn] += y0 * y0 + y2 * y2; cq1[jn] += y1 * y1 + y3 * y3;
            *(float2*)&sc_y[(size_t)r0 * 128 + c] = make_float2(y0, y1);
            *(float2*)&sc_y[(size_t)(r0 + 8) * 128 + c] = make_float2(y2, y3);
        }
        stage ^= 1;
    }

    // reduce stats
    __syncthreads();
#pragma unroll
    for (int jn = 0; jn < 4; jn++) {
        int c = ch * 32 + jn * 8 + (lane & 3) * 2;
        atomicAdd(&sred[c], cs0[jn]);
        atomicAdd(&sred[c + 1], cs1[jn]);
        atomicAdd(&qred[c], cq0[jn]);
        atomicAdd(&qred[c + 1], cq1[jn]);
    }
    __syncthreads();
    if (t < 128) {
        atomicAdd(&sc_sum[t], sred[t]);
        atomicAdd(&sc_ssq[t], qred[t]);
    }
}

// ---------------- apply edge BN + gate, scatter to agg (v4 red) ----------------
__global__ void edge_apply_kernel(const int* __restrict__ dst) {
    int idx = blockIdx.x * blockDim.x + threadIdx.x;
    if (idx >= N_EDGES * 16) return;
    int q = idx & 15;
    int e = idx >> 4;
    int c = q * 4;
    float4 ym = *(const float4*)&sc_y[(size_t)e * 128 + c];
    float4 ys = *(const float4*)&sc_y[(size_t)e * 128 + 64 + c];
    float4 r;
    r.x = sigmoid_f(ym.x * sc_scale[c+0] + sc_shift[c+0]) * softplus_f(ys.x * sc_scale[64+c+0] + sc_shift[64+c+0]);
    r.y = sigmoid_f(ym.y * sc_scale[c+1] + sc_shift[c+1]) * softplus_f(ys.y * sc_scale[64+c+1] + sc_shift[64+c+1]);
    r.z = sigmoid_f(ym.z * sc_scale[c+2] + sc_shift[c+2]) * softplus_f(ys.z * sc_scale[64+c+2] + sc_shift[64+c+2]);
    r.w = sigmoid_f(ym.w * sc_scale[c+3] + sc_shift[c+3]) * softplus_f(ys.w * sc_scale[64+c+3] + sc_shift[64+c+3]);
    red_v4(&sc_agg[dst[e] * D + c], r);
}

__global__ __launch_bounds__(256) void node_stats_kernel() {
    __shared__ float red[256];
    int t = threadIdx.x;
    int c = t & 63, rs = t >> 6;
    float ls = 0.0f, lq = 0.0f;
    const int ntiles = N_NODES / 4;
    for (int ti = blockIdx.x; ti < ntiles; ti += gridDim.x) {
        float y = sc_agg[(ti * 4 + rs) * D + c];
        ls += y; lq += y * y;
    }
    red[t] = ls; __syncthreads();
    if (t < 64) atomicAdd(&sc_sum[t], red[t] + red[t + 64] + red[t + 128] + red[t + 192]);
    __syncthreads();
    red[t] = lq; __syncthreads();
    if (t < 64) atomicAdd(&sc_ssq[t], red[t] + red[t + 64] + red[t + 128] + red[t + 192]);
}

__global__ void node_apply_kernel() {
    int idx = blockIdx.x * blockDim.x + threadIdx.x;
    if (idx < N_NODES * D) {
        int c = idx & 63;
        float x = sc_agg[idx] * sc_scale[c] + sc_shift[c] + sc_v[idx];
        sc_v[idx] = softplus_f(x);
    }
}

__global__ void pool_kernel(const int* __restrict__ gid) {
    int idx = blockIdx.x * blockDim.x + threadIdx.x;
    if (idx >= N_NODES * 16) return;
    int q = idx & 15;
    int n = idx >> 4;
    int c = q * 4;
    int g = gid[n];
    float4 v = *(const float4*)&sc_v[n * D + c];
    red_v4(&sc_pool[g * D + c], v);
    if (q == 0) atomicAdd(&sc_cnt[g], 1.0f);
}
__global__ void pool_finish_kernel() {
    int idx = blockIdx.x * blockDim.x + threadIdx.x;
    if (idx < NG * D) {
        int g = idx >> 6;
        sc_pool[idx] /= fmaxf(sc_cnt[g], 1.0f);
    }
}

__global__ __launch_bounds__(128) void fc_kernel(const float* __restrict__ Wfc, const float* __restrict__ bfc,
                                                 const float* __restrict__ gfc, const float* __restrict__ befc,
                                                 const float* __restrict__ Wout, const float* __restrict__ bout,
                                                 float* __restrict__ out) {
    __shared__ float psh[NG * D];
    __shared__ float red[128];
    int c = threadIdx.x;
    for (int i = c; i < NG * D; i += 128) psh[i] = sc_pool[i];
    __syncthreads();
    float s = 0.0f, q = 0.0f;
    float bc = bfc[c];
    for (int g = 0; g < NG; g++) {
        float acc = bc;
#pragma unroll 8
        for (int k = 0; k < D; k++) acc += psh[g * D + k] * Wfc[k * HDIM + c];
        sc_fcbuf[g * HDIM + c] = acc;
        s += acc; q += acc * acc;
    }
    float mu = s / (float)NG;
    float var = fmaxf(q / (float)NG - mu * mu, 0.0f);
    float sc = gfc[c] * rsqrtf(var + BN_EPS);
    float sh = befc[c] - mu * sc;
    float wo = Wout[c];
    float b0 = bout[0];
    for (int g = 0; g < NG; g++) {
        float y = sc_fcbuf[g * HDIM + c] * sc + sh;
        float val = y * sigmoid_f(y) * wo;
        red[c] = val; __syncthreads();
        for (int st = 64; st > 0; st >>= 1) {
            if (c < st) red[c] += red[c + st];
            __syncthreads();
        }
        if (c == 0) out[g] = red[0] + b0;
        __syncthreads();
    }
}

// ---------------- host launch ----------------
extern "C" void kernel_launch(void* const* d_in, const int* in_sizes, int n_in,
                              void* d_out, int out_size) {
    const float* node_feats = (const float*)d_in[0];
    const float* edge_feats = (const float*)d_in[1];
    const int*   src        = (const int*)d_in[2];
    const int*   dst        = (const int*)d_in[3];
    const int*   gid        = (const int*)d_in[4];
    const float* W_emb  = (const float*)d_in[5];
    const float* b_emb  = (const float*)d_in[6];
    const float* g_emb  = (const float*)d_in[7];
    const float* be_emb = (const float*)d_in[8];
    const float* conv_Wm  = (const float*)d_in[9];
    const float* conv_bm  = (const float*)d_in[10];
    const float* conv_gm  = (const float*)d_in[11];
    const float* conv_bem = (const float*)d_in[12];
    const float* conv_Ws  = (const float*)d_in[13];
    const float* conv_bs  = (const float*)d_in[14];
    const float* conv_gs  = (const float*)d_in[15];
    const float* conv_bes = (const float*)d_in[16];
    const float* conv_gn  = (const float*)d_in[17];
    const float* conv_ben = (const float*)d_in[18];
    const float* W_fc  = (const float*)d_in[19];
    const float* b_fc  = (const float*)d_in[20];
    const float* g_fc  = (const float*)d_in[21];
    const float* be_fc = (const float*)d_in[22];
    const float* W_out = (const float*)d_in[23];
    const float* b_out = (const float*)d_in[24];
    float* out = (float*)d_out;

    cudaFuncSetAttribute(edge_gemm_mma, cudaFuncAttributeMaxDynamicSharedMemorySize, GEMM_DSMEM);

    const int ND = N_NODES * D;
    const int TB = 256;

    efconv_kernel<<<(N_EDGES * EFP + TB - 1) / TB, TB>>>(edge_feats);

    zero_stats_kernel<<<1, 128>>>();
    emb_kernel<<<512, 256>>>(node_feats, W_emb, b_emb);
    scale_kernel<<<1, 64>>>(g_emb, be_emb, (float)N_NODES, 0);
    silu_apply_kernel<<<(ND + TB - 1) / TB, TB>>>();

    for (int l = 0; l < NLAYERS; l++) {
        vconv_kernel<<<(ND + TB - 1) / TB, TB>>>();
        zero_stats_kernel<<<1, 128>>>();
        edge_gemm_mma<<<148, 512, GEMM_DSMEM>>>(src, dst,
            conv_Wm + l * DIN * D, conv_bm + l * D,
            conv_Ws + l * DIN * D, conv_bs + l * D);
        scale_kernel<<<1, 64>>>(conv_gm + l * D, conv_bem + l * D, (float)N_EDGES, 0);
        scale_kernel<<<1, 64>>>(conv_gs + l * D, conv_bes + l * D, (float)N_EDGES, 64);
        zero_agg_kernel<<<(ND / 4 + TB - 1) / TB, TB>>>();
        edge_apply_kernel<<<(N_EDGES * 16 + TB - 1) / TB, TB>>>(dst);
        zero_stats_kernel<<<1, 128>>>();
        node_stats_kernel<<<256, 256>>>();
        scale_kernel<<<1, 64>>>(conv_gn + l * D, conv_ben + l * D, (float)N_NODES, 0);
        node_apply_kernel<<<(ND + TB - 1) / TB, TB>>>();
    }

    zero_pool_kernel<<<(NG * D + TB - 1) / TB, TB>>>();
    pool_kernel<<<(N_NODES * 16 + TB - 1) / TB, TB>>>(gid);
    pool_finish_kernel<<<(NG * D + TB - 1) / TB, TB>>>();
    fc_kernel<<<1, 128>>>(W_fc, b_fc, g_fc, be_fc, W_out, b_out, out);
}

// round 6
// speedup vs baseline: 4.5081x; 1.0090x over previous
#include <cuda_runtime.h>
#include <cuda_bf16.h>
#include <math.h>
#include <stdint.h>

// ---------------- problem constants ----------------
#define N_NODES 50000
#define N_EDGES 800000
#define FN 92
#define FE 41
#define D 64
#define DIN 169
#define NG 100
#define HDIM 128
#define NLAYERS 3
#define BN_EPS 1e-5f

#define KPAD 176                  // 169 padded to 11 chunks of 16
#define EFP 48                    // padded edge-feature width (41 -> 48)
#define TEDGE 64                  // edges per tile
#define NTILES (N_EDGES / TEDGE)  // 12500

// smem geometry (bytes)
#define H_STRIDE 368              // 184 bf16 per row (conflict-free ldmatrix)
#define W_STRIDE 272              // 136 bf16 per row (conflict-free trans ldmatrix)
#define HBUF_B (TEDGE * H_STRIDE) // 23552 per split per stage
#define W_BUF (KPAD * W_STRIDE)   // 47872 per split
#define GEMM_DSMEM (4 * HBUF_B + 2 * W_BUF)   // 189952

// ---------------- device scratch ----------------
__device__ float sc_v[N_NODES * D];
__device__ float sc_y[N_EDGES * 2 * D];
__device__ float sc_agg[N_NODES * D];
__device__ float sc_sum[2 * D];       // edge stats (128)
__device__ float sc_ssq[2 * D];
__device__ float sc_sum2[D];          // node stats (64)
__device__ float sc_ssq2[D];
__device__ float sc_scale[2 * D];
__device__ float sc_shift[2 * D];
__device__ float sc_pool[NG * D];
__device__ float sc_cnt[NG];
__device__ float sc_fcbuf[NG * HDIM];
__device__ int   sc_ctr1;
__device__ int   sc_ctr2;
__device__ __nv_bfloat16 sc_vh[N_NODES * D];
__device__ __nv_bfloat16 sc_vl[N_NODES * D];
__device__ __nv_bfloat16 sc_efh[N_EDGES * EFP];
__device__ __nv_bfloat16 sc_efl[N_EDGES * EFP];

// ---------------- math helpers ----------------
__device__ __forceinline__ float sigmoid_f(float x) { return 1.0f / (1.0f + __expf(-x)); }
__device__ __forceinline__ float softplus_f(float x) {
    return fmaxf(x, 0.0f) + log1pf(__expf(-fabsf(x)));
}
__device__ __forceinline__ void red_v4(float* p, float4 v) {
    asm volatile("red.global.add.v4.f32 [%0], {%1,%2,%3,%4};"
                 :: "l"(p), "f"(v.x), "f"(v.y), "f"(v.z), "f"(v.w) : "memory");
}
__device__ __forceinline__ uint32_t smem_u32(const void* p) {
    uint32_t a;
    asm("{ .reg .u64 t; cvta.to.shared.u64 t, %1; cvt.u32.u64 %0, t; }" : "=r"(a) : "l"(p));
    return a;
}
__device__ __forceinline__ void ldsm_x4(uint32_t addr, uint32_t* r) {
    asm volatile("ldmatrix.sync.aligned.m8n8.x4.shared.b16 {%0,%1,%2,%3}, [%4];"
                 : "=r"(r[0]), "=r"(r[1]), "=r"(r[2]), "=r"(r[3]) : "r"(addr));
}
__device__ __forceinline__ void ldsm_x4_t(uint32_t addr, uint32_t* r) {
    asm volatile("ldmatrix.sync.aligned.m8n8.x4.trans.shared.b16 {%0,%1,%2,%3}, [%4];"
                 : "=r"(r[0]), "=r"(r[1]), "=r"(r[2]), "=r"(r[3]) : "r"(addr));
}
__device__ __forceinline__ void mma_bf16(float* c, const uint32_t* a, uint32_t b0, uint32_t b1) {
    asm volatile("mma.sync.aligned.m16n8k16.row.col.f32.bf16.bf16.f32 "
                 "{%0,%1,%2,%3}, {%4,%5,%6,%7}, {%8,%9}, {%0,%1,%2,%3};"
                 : "+f"(c[0]), "+f"(c[1]), "+f"(c[2]), "+f"(c[3])
                 : "r"(a[0]), "r"(a[1]), "r"(a[2]), "r"(a[3]), "r"(b0), "r"(b1));
}
__device__ __forceinline__ void cpa16(uint32_t saddr, const void* g) {
    asm volatile("cp.async.ca.shared.global [%0], [%1], 16;" :: "r"(saddr), "l"(g));
}
#define CP_COMMIT() asm volatile("cp.async.commit_group;" ::: "memory")
#define CP_WAIT(n)  asm volatile("cp.async.wait_group %0;" :: "n"(n) : "memory")

// coherent read of atomically-accumulated value
__device__ __forceinline__ float atomic_read(float* p) { return atomicAdd(p, 0.0f); }

// ---------------- zero / split helpers ----------------
__device__ __forceinline__ void layer_zeros(int i) {
    if (i < N_NODES * D / 4) ((float4*)sc_agg)[i] = make_float4(0.f, 0.f, 0.f, 0.f);
    if (i < 128) { sc_sum[i] = 0.0f; sc_ssq[i] = 0.0f; }
    if (i < 64)  { sc_sum2[i] = 0.0f; sc_ssq2[i] = 0.0f; }
    if (i < NG * D) sc_pool[i] = 0.0f;
    if (i < NG) sc_cnt[i] = 0.0f;
    if (i == 0) { sc_ctr1 = 0; sc_ctr2 = 0; }
}
__device__ __forceinline__ void v_split(int i) {
    if (i < N_NODES * D) {
        float x = sc_v[i];
        __nv_bfloat16 h = __float2bfloat16(x);
        sc_vh[i] = h;
        sc_vl[i] = __float2bfloat16(x - __bfloat162float(h));
    }
}

__global__ void zero_stats_kernel() {
    int t = threadIdx.x;
    if (t < 128) { sc_sum[t] = 0.0f; sc_ssq[t] = 0.0f; }
    if (t < 64)  { sc_sum2[t] = 0.0f; sc_ssq2[t] = 0.0f; }
    if (t == 0)  { sc_ctr1 = 0; sc_ctr2 = 0; }
}

__global__ void scale_kernel(const float* __restrict__ gamma, const float* __restrict__ beta,
                             float count, int off) {
    int t = threadIdx.x;
    float mu = sc_sum[off + t] / count;
    float var = fmaxf(sc_ssq[off + t] / count - mu * mu, 0.0f);
    float s = gamma[t] * rsqrtf(var + BN_EPS);
    sc_scale[off + t] = s;
    sc_shift[off + t] = beta[t] - mu * s;
}

// layer 0 prep: ef split + v split + all zeros
__global__ void prep0_kernel(const float* __restrict__ ef) {
    int i = blockIdx.x * blockDim.x + threadIdx.x;
    if (i < N_EDGES * EFP) {
        int e = i / EFP, j = i - e * EFP;
        float x = (j < FE) ? ef[(size_t)e * FE + j] : 0.0f;
        __nv_bfloat16 h = __float2bfloat16(x);
        sc_efh[i] = h;
        sc_efl[i] = __float2bfloat16(x - __bfloat162float(h));
    }
    v_split(i);
    layer_zeros(i);
}

// layers 1..: v split + zeros
__global__ void vconv_kernel() {
    int i = blockIdx.x * blockDim.x + threadIdx.x;
    v_split(i);
    layer_zeros(i);
}

// ---------------- node embedding GEMM (fp32, small) ----------------
__global__ __launch_bounds__(256) void emb_kernel(const float* __restrict__ x,
                                                  const float* __restrict__ W,
                                                  const float* __restrict__ b) {
    __shared__ float Wsh[FN * D];
    __shared__ float xsh[4][FN];
    __shared__ float red[256];
    int t = threadIdx.x;
    for (int i = t; i < FN * D; i += 256) Wsh[i] = W[i];
    int c = t & 63, rs = t >> 6;
    float bc = b[c];
    float ls = 0.0f, lq = 0.0f;
    const int ntiles = N_NODES / 4;
    for (int ti = blockIdx.x; ti < ntiles; ti += gridDim.x) {
        int r0 = ti * 4;
        __syncthreads();
        for (int i = t; i < 4 * FN; i += 256) {
            int rr = i / FN, k = i - rr * FN;
            xsh[rr][k] = x[(r0 + rr) * FN + k];
        }
        __syncthreads();
        float acc = bc;
#pragma unroll 4
        for (int k = 0; k < FN; k++) acc += xsh[rs][k] * Wsh[k * D + c];
        sc_v[(r0 + rs) * D + c] = acc;
        ls += acc; lq += acc * acc;
    }
    __syncthreads();
    red[t] = ls; __syncthreads();
    if (t < 64) atomicAdd(&sc_sum[t], red[t] + red[t + 64] + red[t + 128] + red[t + 192]);
    __syncthreads();
    red[t] = lq; __syncthreads();
    if (t < 64) atomicAdd(&sc_ssq[t], red[t] + red[t + 64] + red[t + 128] + red[t + 192]);
}

__global__ void silu_apply_kernel() {
    int idx = blockIdx.x * blockDim.x + threadIdx.x;
    if (idx < N_NODES * D) {
        int c = idx & 63;
        float y = sc_v[idx] * sc_scale[c] + sc_shift[c];
        sc_v[idx] = y * sigmoid_f(y);
    }
}

// ---------------- pipelined HMMA edge GEMM + last-CTA BN scale ----------------
__device__ __forceinline__ void issue_h(uint32_t smb_u, int st, int e0,
                                        const int* ssrc, const int* sdst, int t) {
    uint32_t base_hi = smb_u + (uint32_t)(st * 2) * HBUF_B;
    uint32_t base_lo = base_hi + HBUF_B;
    for (int i = t; i < 44 * TEDGE; i += 512) {
        int slot = i >> 6, row = i & 63;
        int lobuf = slot >= 22;
        int s0 = lobuf ? slot - 22 : slot;
        const __nv_bfloat16* g;
        uint32_t k0;
        if (s0 < 8) {
            g = (lobuf ? sc_vl : sc_vh) + ssrc[row] * D + s0 * 8;
            k0 = (uint32_t)s0 * 8;
        } else if (s0 < 16) {
            g = (lobuf ? sc_vl : sc_vh) + sdst[row] * D + (s0 - 8) * 8;
            k0 = 64 + (uint32_t)(s0 - 8) * 8;
        } else {
            g = (lobuf ? sc_efl : sc_efh) + (size_t)(e0 + row) * EFP + (s0 - 16) * 8;
            k0 = 128 + (uint32_t)(s0 - 16) * 8;
        }
        cpa16((lobuf ? base_lo : base_hi) + (uint32_t)row * H_STRIDE + k0 * 2, g);
    }
}

__global__ __launch_bounds__(512, 1) void edge_gemm_mma(const int* __restrict__ src,
                                                        const int* __restrict__ dst,
                                                        const float* __restrict__ Wm,
                                                        const float* __restrict__ bm,
                                                        const float* __restrict__ Ws,
                                                        const float* __restrict__ bs,
                                                        const float* __restrict__ gm,
                                                        const float* __restrict__ bem,
                                                        const float* __restrict__ gs,
                                                        const float* __restrict__ bes) {
    extern __shared__ char smb[];
    uint32_t smb_u = smem_u32(smb);
    char* w_hi = smb + 4 * HBUF_B;
    char* w_lo = w_hi + W_BUF;
    uint32_t w_hi_u = smb_u + 4 * HBUF_B;
    uint32_t w_lo_u = w_hi_u + W_BUF;
    __shared__ int sidx[2][2][TEDGE];
    __shared__ float sred[128], qred[128];
    __shared__ int islast;

    int t = threadIdx.x;
    int lane = t & 31;
    int wid = t >> 5;
    int eg = wid & 3;
    int ch = wid >> 2;

    if (t < 128) { sred[t] = 0.0f; qred[t] = 0.0f; }

    for (int i = t; i < 2 * W_BUF / 16; i += 512)
        ((uint4*)w_hi)[i] = make_uint4(0, 0, 0, 0);
    __syncthreads();

    for (int i = t; i < DIN * 128; i += 512) {
        int c = i & 127, k = i >> 7;
        float wv = (c < 64) ? Wm[k * 64 + c] : Ws[k * 64 + (c - 64)];
        __nv_bfloat16 hi = __float2bfloat16(wv);
        __nv_bfloat16 lo = __float2bfloat16(wv - __bfloat162float(hi));
        uint32_t byte = (uint32_t)k * W_STRIDE + (uint32_t)c * 2;
        *(__nv_bfloat16*)(w_hi + byte) = hi;
        *(__nv_bfloat16*)(w_lo + byte) = lo;
    }

    float bias0[4], bias1[4];
#pragma unroll
    for (int jn = 0; jn < 4; jn++) {
        int c = ch * 32 + jn * 8 + (lane & 3) * 2;
        bias0[jn] = (c < 64) ? bm[c] : bs[c - 64];
        bias1[jn] = (c + 1 < 64) ? bm[c + 1] : bs[c + 1 - 64];
    }
    float cs0[4], cs1[4], cq0[4], cq1[4];
#pragma unroll
    for (int jn = 0; jn < 4; jn++) { cs0[jn] = cs1[jn] = cq0[jn] = cq1[jn] = 0.0f; }

    uint32_t a_off = (uint32_t)(eg * 16 + (lane & 15)) * H_STRIDE + (uint32_t)(lane >> 4) * 16;
    uint32_t b_off = (uint32_t)((lane & 7) + ((lane >> 3) & 1) * 8) * W_STRIDE +
                     (uint32_t)(ch * 32 + (lane >> 4) * 8) * 2;

    const int GRID = gridDim.x;
    int ti0 = blockIdx.x;

    if (t < 64) sidx[0][0][t] = src[ti0 * TEDGE + t];
    else if (t < 128) sidx[0][1][t - 64] = dst[ti0 * TEDGE + t - 64];
    __syncthreads();
    issue_h(smb_u, 0, ti0 * TEDGE, sidx[0][0], sidx[0][1], t);
    CP_COMMIT();

    int stage = 0;
    for (int ti = ti0; ti < NTILES; ti += GRID) {
        int tn = ti + GRID;
        if (tn < NTILES) {
            __syncthreads();
            if (t < 64) sidx[stage ^ 1][0][t] = src[tn * TEDGE + t];
            else if (t < 128) sidx[stage ^ 1][1][t - 64] = dst[tn * TEDGE + t - 64];
            __syncthreads();
            issue_h(smb_u, stage ^ 1, tn * TEDGE, sidx[stage ^ 1][0], sidx[stage ^ 1][1], t);
            CP_COMMIT();
            CP_WAIT(1);
        } else {
            CP_WAIT(0);
        }
        __syncthreads();

        uint32_t hb_hi = smb_u + (uint32_t)(stage * 2) * HBUF_B + a_off;
        uint32_t hb_lo = hb_hi + HBUF_B;

        float acc[4][4];
#pragma unroll
        for (int jn = 0; jn < 4; jn++) { acc[jn][0] = acc[jn][1] = acc[jn][2] = acc[jn][3] = 0.0f; }

#pragma unroll
        for (int kc = 0; kc < 11; kc++) {
            uint32_t ah[4], al[4];
            ldsm_x4(hb_hi + (uint32_t)kc * 32, ah);
            ldsm_x4(hb_lo + (uint32_t)kc * 32, al);
#pragma unroll
            for (int jp = 0; jp < 2; jp++) {
                uint32_t bh[4], bl[4];
                uint32_t boff = (uint32_t)kc * 16 * W_STRIDE + b_off + (uint32_t)jp * 32;
                ldsm_x4_t(w_hi_u + boff, bh);
                ldsm_x4_t(w_lo_u + boff, bl);
                mma_bf16(acc[2 * jp],     ah, bh[0], bh[1]);
                mma_bf16(acc[2 * jp + 1], ah, bh[2], bh[3]);
                mma_bf16(acc[2 * jp],     al, bh[0], bh[1]);
                mma_bf16(acc[2 * jp + 1], al, bh[2], bh[3]);
                mma_bf16(acc[2 * jp],     ah, bl[0], bl[1]);
                mma_bf16(acc[2 * jp + 1], ah, bl[2], bl[3]);
            }
        }

        int r0 = ti * TEDGE + eg * 16 + (lane >> 2);
#pragma unroll
        for (int jn = 0; jn < 4; jn++) {
            int c = ch * 32 + jn * 8 + (lane & 3) * 2;
            float y0 = acc[jn][0] + bias0[jn];
            float y1 = acc[jn][1] + bias1[jn];
            float y2 = acc[jn][2] + bias0[jn];
            float y3 = acc[jn][3] + bias1[jn];
            cs0[jn] += y0 + y2; cs1[jn] += y1 + y3;
            cq0[jn] += y0 * y0 + y2 * y2; cq1[jn] += y1 * y1 + y3 * y3;
            *(float2*)&sc_y[(size_t)r0 * 128 + c] = make_float2(y0, y1);
            *(float2*)&sc_y[(size_t)(r0 + 8) * 128 + c] = make_float2(y2, y3);
        }
        stage ^= 1;
    }

    // reduce stats
    __syncthreads();
#pragma unroll
    for (int jn = 0; jn < 4; jn++) {
        int c = ch * 32 + jn * 8 + (lane & 3) * 2;
        atomicAdd(&sred[c], cs0[jn]);
        atomicAdd(&sred[c + 1], cs1[jn]);
        atomicAdd(&qred[c], cq0[jn]);
        atomicAdd(&qred[c + 1], cq1[jn]);
    }
    __syncthreads();
    if (t < 128) {
        atomicAdd(&sc_sum[t], sred[t]);
        atomicAdd(&sc_ssq[t], qred[t]);
    }

    // last CTA computes edge BN scale/shift
    __threadfence();
    __syncthreads();
    if (t == 0) islast = (atomicAdd(&sc_ctr1, 1) == (int)gridDim.x - 1);
    __syncthreads();
    if (islast && t < 128) {
        float s = atomic_read(&sc_sum[t]);
        float q = atomic_read(&sc_ssq[t]);
        float mu = s / (float)N_EDGES;
        float var = fmaxf(q / (float)N_EDGES - mu * mu, 0.0f);
        float gam = (t < 64) ? gm[t] : gs[t - 64];
        float bet = (t < 64) ? bem[t] : bes[t - 64];
        float sc = gam * rsqrtf(var + BN_EPS);
        sc_scale[t] = sc;
        sc_shift[t] = bet - mu * sc;
    }
}

// ---------------- apply edge BN + gate, scatter to agg (v4 red) ----------------
__global__ void edge_apply_kernel(const int* __restrict__ dst) {
    int idx = blockIdx.x * blockDim.x + threadIdx.x;
    if (idx >= N_EDGES * 16) return;
    int q = idx & 15;
    int e = idx >> 4;
    int c = q * 4;
    float4 ym = *(const float4*)&sc_y[(size_t)e * 128 + c];
    float4 ys = *(const float4*)&sc_y[(size_t)e * 128 + 64 + c];
    float4 r;
    r.x = sigmoid_f(ym.x * sc_scale[c+0] + sc_shift[c+0]) * softplus_f(ys.x * sc_scale[64+c+0] + sc_shift[64+c+0]);
    r.y = sigmoid_f(ym.y * sc_scale[c+1] + sc_shift[c+1]) * softplus_f(ys.y * sc_scale[64+c+1] + sc_shift[64+c+1]);
    r.z = sigmoid_f(ym.z * sc_scale[c+2] + sc_shift[c+2]) * softplus_f(ys.z * sc_scale[64+c+2] + sc_shift[64+c+2]);
    r.w = sigmoid_f(ym.w * sc_scale[c+3] + sc_shift[c+3]) * softplus_f(ys.w * sc_scale[64+c+3] + sc_shift[64+c+3]);
    red_v4(&sc_agg[dst[e] * D + c], r);
}

// ---------------- node stats + last-block node BN scale ----------------
__global__ __launch_bounds__(256) void node_stats_kernel(const float* __restrict__ gn,
                                                         const float* __restrict__ ben) {
    __shared__ float red[256];
    __shared__ int islast;
    int t = threadIdx.x;
    int c = t & 63, rs = t >> 6;
    float ls = 0.0f, lq = 0.0f;
    const int ntiles = N_NODES / 4;
    for (int ti = blockIdx.x; ti < ntiles; ti += gridDim.x) {
        float y = sc_agg[(ti * 4 + rs) * D + c];
        ls += y; lq += y * y;
    }
    red[t] = ls; __syncthreads();
    if (t < 64) atomicAdd(&sc_sum2[t], red[t] + red[t + 64] + red[t + 128] + red[t + 192]);
    __syncthreads();
    red[t] = lq; __syncthreads();
    if (t < 64) atomicAdd(&sc_ssq2[t], red[t] + red[t + 64] + red[t + 128] + red[t + 192]);

    __threadfence();
    __syncthreads();
    if (t == 0) islast = (atomicAdd(&sc_ctr2, 1) == (int)gridDim.x - 1);
    __syncthreads();
    if (islast && t < 64) {
        float s = atomic_read(&sc_sum2[t]);
        float q = atomic_read(&sc_ssq2[t]);
        float mu = s / (float)N_NODES;
        float var = fmaxf(q / (float)N_NODES - mu * mu, 0.0f);
        float sc = gn[t] * rsqrtf(var + BN_EPS);
        sc_scale[t] = sc;
        sc_shift[t] = ben[t] - mu * sc;
    }
}

__global__ void node_apply_kernel() {
    int idx = blockIdx.x * blockDim.x + threadIdx.x;
    if (idx < N_NODES * D) {
        int c = idx & 63;
        float x = sc_agg[idx] * sc_scale[c] + sc_shift[c] + sc_v[idx];
        sc_v[idx] = softplus_f(x);
    }
}

__global__ void pool_kernel(const int* __restrict__ gid) {
    int idx = blockIdx.x * blockDim.x + threadIdx.x;
    if (idx >= N_NODES * 16) return;
    int q = idx & 15;
    int n = idx >> 4;
    int c = q * 4;
    int g = gid[n];
    float4 v = *(const float4*)&sc_v[n * D + c];
    red_v4(&sc_pool[g * D + c], v);
    if (q == 0) atomicAdd(&sc_cnt[g], 1.0f);
}

__global__ __launch_bounds__(128) void fc_kernel(const float* __restrict__ Wfc, const float* __restrict__ bfc,
                                                 const float* __restrict__ gfc, const float* __restrict__ befc,
                                                 const float* __restrict__ Wout, const float* __restrict__ bout,
                                                 float* __restrict__ out) {
    __shared__ float psh[NG * D];
    __shared__ float red[128];
    int c = threadIdx.x;
    for (int i = c; i < NG * D; i += 128)
        psh[i] = sc_pool[i] / fmaxf(sc_cnt[i / D], 1.0f);
    __syncthreads();
    float s = 0.0f, q = 0.0f;
    float bc = bfc[c];
    for (int g = 0; g < NG; g++) {
        float acc = bc;
#pragma unroll 8
        for (int k = 0; k < D; k++) acc += psh[g * D + k] * Wfc[k * HDIM + c];
        sc_fcbuf[g * HDIM + c] = acc;
        s += acc; q += acc * acc;
    }
    float mu = s / (float)NG;
    float var = fmaxf(q / (float)NG - mu * mu, 0.0f);
    float sc = gfc[c] * rsqrtf(var + BN_EPS);
    float sh = befc[c] - mu * sc;
    float wo = Wout[c];
    float b0 = bout[0];
    for (int g = 0; g < NG; g++) {
        float y = sc_fcbuf[g * HDIM + c] * sc + sh;
        float val = y * sigmoid_f(y) * wo;
        red[c] = val; __syncthreads();
        for (int st = 64; st > 0; st >>= 1) {
            if (c < st) red[c] += red[c + st];
            __syncthreads();
        }
        if (c == 0) out[g] = red[0] + b0;
        __syncthreads();
    }
}

// ---------------- host launch ----------------
extern "C" void kernel_launch(void* const* d_in, const int* in_sizes, int n_in,
                              void* d_out, int out_size) {
    const float* node_feats = (const float*)d_in[0];
    const float* edge_feats = (const float*)d_in[1];
    const int*   src        = (const int*)d_in[2];
    const int*   dst        = (const int*)d_in[3];
    const int*   gid        = (const int*)d_in[4];
    const float* W_emb  = (const float*)d_in[5];
    const float* b_emb  = (const float*)d_in[6];
    const float* g_emb  = (const float*)d_in[7];
    const float* be_emb = (const float*)d_in[8];
    const float* conv_Wm  = (const float*)d_in[9];
    const float* conv_bm  = (const float*)d_in[10];
    const float* conv_gm  = (const float*)d_in[11];
    const float* conv_bem = (const float*)d_in[12];
    const float* conv_Ws  = (const float*)d_in[13];
    const float* conv_bs  = (const float*)d_in[14];
    const float* conv_gs  = (const float*)d_in[15];
    const float* conv_bes = (const float*)d_in[16];
    const float* conv_gn  = (const float*)d_in[17];
    const float* conv_ben = (const float*)d_in[18];
    const float* W_fc  = (const float*)d_in[19];
    const float* b_fc  = (const float*)d_in[20];
    const float* g_fc  = (const float*)d_in[21];
    const float* be_fc = (const float*)d_in[22];
    const float* W_out = (const float*)d_in[23];
    const float* b_out = (const float*)d_in[24];
    float* out = (float*)d_out;

    cudaFuncSetAttribute(edge_gemm_mma, cudaFuncAttributeMaxDynamicSharedMemorySize, GEMM_DSMEM);

    const int ND = N_NODES * D;
    const int TB = 256;

    // 1..5: zstats, emb, scale_emb, silu, prep0  (launch 6 = GEMM for ncu -s 5)
    zero_stats_kernel<<<1, 128>>>();
    emb_kernel<<<512, 256>>>(node_feats, W_emb, b_emb);
    scale_kernel<<<1, 64>>>(g_emb, be_emb, (float)N_NODES, 0);
    silu_apply_kernel<<<(ND + TB - 1) / TB, TB>>>();
    prep0_kernel<<<(N_EDGES * EFP + TB - 1) / TB, TB>>>(edge_feats);

    for (int l = 0; l < NLAYERS; l++) {
        if (l > 0) vconv_kernel<<<(ND + TB - 1) / TB, TB>>>();
        edge_gemm_mma<<<148, 512, GEMM_DSMEM>>>(src, dst,
            conv_Wm + l * DIN * D, conv_bm + l * D,
            conv_Ws + l * DIN * D, conv_bs + l * D,
            conv_gm + l * D, conv_bem + l * D,
            conv_gs + l * D, conv_bes + l * D);
        edge_apply_kernel<<<(N_EDGES * 16 + TB - 1) / TB, TB>>>(dst);
        node_stats_kernel<<<256, 256>>>(conv_gn + l * D, conv_ben + l * D);
        node_apply_kernel<<<(ND + TB - 1) / TB, TB>>>();
    }

    pool_kernel<<<(N_NODES * 16 + TB - 1) / TB, TB>>>(gid);
    fc_kernel<<<1, 128>>>(W_fc, b_fc, g_fc, be_fc, W_out, b_out, out);
}